// round 2
// baseline (speedup 1.0000x reference)
#include <cuda_runtime.h>
#include <math.h>

#define NB    4
#define NLL   2048
#define NCOLS 1024
#define NHEAD 16
#define HDIM  64
#define CK    16
#define NCH   128
#define F4C   256
#define EPSV  1e-6f

// ---------------------------------------------------------------------------
// Device-global scratch (allocation-free per harness rules)
// ---------------------------------------------------------------------------
__device__ float g_XQ[NB*NHEAD*NCH*CK*HDIM];
__device__ float g_XK[NB*NHEAD*NCH*CK*HDIM];
__device__ float g_XV[NB*NHEAD*NCH*CK*HDIM];
__device__ float g_lr[NB*NHEAD*NCH*CK];
__device__ float g_XQW[NB*NLL*NCOLS];
__device__ float g_norm[NB*NLL*NCOLS];

// ---------------------------------------------------------------------------
__device__ __forceinline__ float warp_sum(float v) {
#pragma unroll
    for (int o = 16; o > 0; o >>= 1) v += __shfl_xor_sync(0xffffffffu, v, o);
    return v;
}

__device__ __forceinline__ float tanh_fast(float x) {
    float e = __expf(2.0f * x);
    return (e - 1.0f) / (e + 1.0f);
}
__device__ __forceinline__ float gelu_f(float x) {
    float t = tanh_fast(0.79788456f * x * (1.0f + 0.044715f * x * x));
    return 0.5f * x * (1.0f + t);
}
__device__ __forceinline__ float gelu_bwd_f(float x) {
    float t = tanh_fast(0.79788456f * x * (1.0f + 0.044715f * x * x));
    return 0.5f * x * ((1.0f - t * t) * (0.79788456f + 0.1070322243f * x * x))
         + 0.5f * (1.0f + t);
}

// ---------------------------------------------------------------------------
// K1: QKV projection GEMM + RoPE + scatter.  out[m][n] = dot(hs[m], W[n])
// grid (16, 128, 3), 256 thr, 64x64 tile, 4x4 microtile
// ---------------------------------------------------------------------------
__global__ void __launch_bounds__(256) qkv_kernel(
    const float* __restrict__ hs,
    const float* __restrict__ wq,
    const float* __restrict__ wk,
    const float* __restrict__ wv)
{
    __shared__ float As[16][68];
    __shared__ float Bs[16][68];

    const int z = blockIdx.z;
    const float* W = (z == 0) ? wq : ((z == 1) ? wk : wv);
    float* dst = (z == 0) ? g_XQ : ((z == 1) ? g_XK : g_XV);

    const int mT = blockIdx.y * 64;
    const int nT = blockIdx.x * 64;
    const int tid = threadIdx.x;

    const int ldr = tid >> 2;          // 0..63
    const int ldc = (tid & 3) * 4;     // 0,4,8,12
    const float* Ap = hs + (size_t)(mT + ldr) * NCOLS + ldc;
    const float* Bp = W  + (size_t)(nT + ldr) * NCOLS + ldc;

    const int r0 = (tid >> 4) * 4;
    const int c0 = (tid & 15) * 4;

    float acc[4][4];
#pragma unroll
    for (int r = 0; r < 4; r++)
#pragma unroll
        for (int c = 0; c < 4; c++) acc[r][c] = 0.0f;

    for (int kt = 0; kt < 64; kt++) {
        float4 a = *(const float4*)(Ap + kt * 16);
        float4 b = *(const float4*)(Bp + kt * 16);
        As[ldc+0][ldr] = a.x; As[ldc+1][ldr] = a.y;
        As[ldc+2][ldr] = a.z; As[ldc+3][ldr] = a.w;
        Bs[ldc+0][ldr] = b.x; Bs[ldc+1][ldr] = b.y;
        Bs[ldc+2][ldr] = b.z; Bs[ldc+3][ldr] = b.w;
        __syncthreads();
#pragma unroll
        for (int kk = 0; kk < 16; kk++) {
            float4 av = *(const float4*)&As[kk][r0];
            float4 bv = *(const float4*)&Bs[kk][c0];
            float ar[4] = {av.x, av.y, av.z, av.w};
            float br[4] = {bv.x, bv.y, bv.z, bv.w};
#pragma unroll
            for (int r = 0; r < 4; r++)
#pragma unroll
                for (int c = 0; c < 4; c++) acc[r][c] += ar[r] * br[c];
        }
        __syncthreads();
    }

    // Epilogue: RoPE (q,k) + scatter to [bh][n][k][d]
#pragma unroll
    for (int rr = 0; rr < 4; rr++) {
        int m   = mT + r0 + rr;
        int pos = m & 15;
        int bb  = m >> 11;
        int l   = m & 2047;
        int nch = l >> 4;
        int kk  = l & 15;
#pragma unroll
        for (int p = 0; p < 2; p++) {
            int n0 = nT + c0 + 2 * p;
            int h  = n0 >> 6;
            int d  = n0 & 63;
            float x0 = acc[rr][2*p], x1 = acc[rr][2*p+1];
            size_t base = ((((size_t)(bb*NHEAD + h))*NCH + nch)*CK + kk)*HDIM + d;
            if (z < 2) {
                float ang = (float)pos * powf(10000.0f, -((float)d) * (1.0f/64.0f));
                float sn, cs;
                sincosf(ang, &sn, &cs);
                dst[base]   = x0 * cs - x1 * sn;
                dst[base+1] = x0 * sn + x1 * cs;
            } else {
                dst[base]   = x0;
                dst[base+1] = x1;
            }
        }
    }
}

// ---------------------------------------------------------------------------
// K2: ttt_lr = sigmoid(hs . lrw[h] + lrb[h]) / HD    grid 8192, 256 thr
// ---------------------------------------------------------------------------
__global__ void __launch_bounds__(256) lr_kernel(
    const float* __restrict__ hs,
    const float* __restrict__ lrw,
    const float* __restrict__ lrb)
{
    int row = blockIdx.x;
    int w = threadIdx.x >> 5, lane = threadIdx.x & 31;
    const float4* x4 = (const float4*)(hs + (size_t)row * NCOLS);
    for (int h = w; h < NHEAD; h += 8) {
        const float4* w4 = (const float4*)(lrw + (size_t)h * NCOLS);
        float acc = 0.0f;
        for (int c = lane; c < 256; c += 32) {
            float4 a = x4[c], b = w4[c];
            acc += a.x*b.x + a.y*b.y + a.z*b.z + a.w*b.w;
        }
        acc = warp_sum(acc);
        if (lane == 0) {
            float v = 1.0f / (1.0f + __expf(-(acc + lrb[h])));
            int b = row >> 11, l = row & 2047, n = l >> 4, k = l & 15;
            g_lr[(((size_t)(b*NHEAD + h))*NCH + n)*CK + k] = v * (1.0f/64.0f);
        }
    }
}

// ---------------------------------------------------------------------------
// K3: the sequential TTT scan.  One CTA per (b,h), state in smem.
// ---------------------------------------------------------------------------
struct ScanSmem {
    float W1[64*256];    // [d][f]
    float W2[256*65];    // [f][d] pad 65
    float b1[256];
    float b2[64];
    float xq[16*65];
    float xk[16*65];
    float tg[16*65];     // xv - xk
    float Z1[16*260];    // raw Z1, later reused as X2_bar
    float X2[16*260];
    float gZ1[16*260];
    float Z2[16*65];
    float gZ2[16*65];
    float Z2b[16*65];
    float A1e[256];
    float A2e[256];
    float lr[16];
    float le[16];        // last_eta
    float tok[16];
    float lnw[64];
    float lnb[64];
};

__global__ void __launch_bounds__(256, 1) scan_kernel(
    const float* __restrict__ W1g, const float* __restrict__ b1g,
    const float* __restrict__ W2g, const float* __restrict__ b2g,
    const float* __restrict__ lnwg, const float* __restrict__ lnbg,
    const float* __restrict__ ltig)
{
    extern __shared__ float smraw[];
    ScanSmem& s = *reinterpret_cast<ScanSmem*>(smraw);

    const int tid = threadIdx.x;
    const int bh  = blockIdx.x;
    const int b   = bh >> 4;
    const int h   = bh & 15;

    // ---- init state ----
    for (int i = tid; i < 16384; i += 256) s.W1[i] = W1g[(size_t)h*16384 + i];
    for (int i = tid; i < 16384; i += 256) {
        int f = i >> 6, d = i & 63;
        s.W2[f*65 + d] = W2g[(size_t)h*16384 + i];
    }
    s.b1[tid] = b1g[h*256 + tid];
    if (tid < 64) {
        s.b2[tid]  = b2g[h*64 + tid];
        s.lnw[tid] = lnwg[h*64 + tid];
        s.lnb[tid] = lnbg[h*64 + tid];
    }
    if (tid < 16) s.tok[tid] = fmaxf(1.0f/(float)(tid+1) + ltig[tid], 0.0f);
    __syncthreads();

    const int igrp = tid >> 6;        // 0..3
    const int fgrp = tid & 63;        // 0..63
    const int f0   = fgrp << 2;
    const int wi   = tid >> 5;        // warp 0..7
    const int lane = tid & 31;

    for (int n = 0; n < NCH; n++) {
        // ---- phase 0a: load chunk ----
        const float* pq = g_XQ + ((size_t)bh*NCH + n)*1024;
        const float* pk = g_XK + ((size_t)bh*NCH + n)*1024;
        const float* pv = g_XV + ((size_t)bh*NCH + n)*1024;
        for (int idx = tid; idx < 1024; idx += 256) {
            int k = idx >> 6, d = idx & 63;
            float kv = pk[idx];
            s.xq[k*65+d] = pq[idx];
            s.xk[k*65+d] = kv;
            s.tg[k*65+d] = pv[idx] - kv;
        }
        if (tid < 16) {
            float v = g_lr[((size_t)bh*NCH + n)*CK + tid];
            s.lr[tid] = v;
            s.le[tid] = s.tok[15] * v;
        }
        __syncthreads();

        // ---- phase 0b: A1e[i][j] = tok[i]*lr[j]*(xq_i . xk_j + 1)  (j<=i) ----
        {
            int i = tid >> 4, j = tid & 15;
            float acc = 0.0f;
#pragma unroll 16
            for (int d = 0; d < 64; d++) acc += s.xq[i*65+d] * s.xk[j*65+d];
            s.A1e[tid] = (j <= i) ? s.tok[i]*s.lr[j]*(acc + 1.0f) : 0.0f;
        }

        // ---- phase 1: Z1 = xk@W1 + b1 ; X2 = gelu(Z1) ----
        {
            float acc[4][4];
            float4 bb = *(const float4*)&s.b1[f0];
#pragma unroll
            for (int r = 0; r < 4; r++) {
                acc[r][0]=bb.x; acc[r][1]=bb.y; acc[r][2]=bb.z; acc[r][3]=bb.w;
            }
#pragma unroll 8
            for (int d = 0; d < 64; d++) {
                float4 w = *(const float4*)&s.W1[d*256 + f0];
#pragma unroll
                for (int r = 0; r < 4; r++) {
                    float a = s.xk[(igrp*4+r)*65 + d];
                    acc[r][0] += a*w.x; acc[r][1] += a*w.y;
                    acc[r][2] += a*w.z; acc[r][3] += a*w.w;
                }
            }
#pragma unroll
            for (int r = 0; r < 4; r++) {
                int i = igrp*4 + r;
                float4 z = make_float4(acc[r][0], acc[r][1], acc[r][2], acc[r][3]);
                *(float4*)&s.Z1[i*260 + f0] = z;
                float4 g = make_float4(gelu_f(z.x), gelu_f(z.y), gelu_f(z.z), gelu_f(z.w));
                *(float4*)&s.X2[i*260 + f0] = g;
            }
        }
        __syncthreads();

        // ---- phase 2: Z2 = X2@W2 + b2 ----
        {
            int ii = tid >> 6, d = tid & 63;
            float bv = s.b2[d];
            float acc[4] = {bv, bv, bv, bv};
#pragma unroll 4
            for (int f = 0; f < 256; f++) {
                float w = s.W2[f*65 + d];
#pragma unroll
                for (int r = 0; r < 4; r++) acc[r] += s.X2[(ii+4*r)*260 + f] * w;
            }
#pragma unroll
            for (int r = 0; r < 4; r++) s.Z2[(ii+4*r)*65 + d] = acc[r];
        }
        __syncthreads();

        // ---- phase 3: gZ2 = ln_fused_l2_bwd(Z2, tgt) ----
        for (int rr = 0; rr < 2; rr++) {
            int i = wi*2 + rr;
            float z0 = s.Z2[i*65 + lane], z1 = s.Z2[i*65 + lane + 32];
            float mu = warp_sum(z0 + z1) * (1.0f/64.0f);
            float d0 = z0 - mu, d1 = z1 - mu;
            float var = warp_sum(d0*d0 + d1*d1) * (1.0f/64.0f);
            float rstd = rsqrtf(var + EPSV);
            float xh0 = d0*rstd, xh1 = d1*rstd;
            float w0 = s.lnw[lane], w1 = s.lnw[lane+32];
            float go0 = (w0*xh0 + s.lnb[lane]    - s.tg[i*65+lane   ]) * w0;
            float go1 = (w1*xh1 + s.lnb[lane+32] - s.tg[i*65+lane+32]) * w1;
            float sgo = warp_sum(go0 + go1);
            float sgx = warp_sum(go0*xh0 + go1*xh1);
            float sc = rstd * (1.0f/64.0f);
            s.gZ2[i*65+lane]    = (64.0f*go0 - sgo - xh0*sgx) * sc;
            s.gZ2[i*65+lane+32] = (64.0f*go1 - sgo - xh1*sgx) * sc;
        }
        __syncthreads();

        // ---- phase 4: gZ1 = (gZ2 @ W2^T) * gelu_bwd(Z1) ----
        {
            float acc[4][4];
#pragma unroll
            for (int r = 0; r < 4; r++)
#pragma unroll
                for (int q = 0; q < 4; q++) acc[r][q] = 0.0f;
#pragma unroll 4
            for (int d = 0; d < 64; d++) {
                float g[4];
#pragma unroll
                for (int r = 0; r < 4; r++) g[r] = s.gZ2[(igrp*4+r)*65 + d];
#pragma unroll
                for (int q = 0; q < 4; q++) {
                    float w = s.W2[(fgrp + 64*q)*65 + d];
#pragma unroll
                    for (int r = 0; r < 4; r++) acc[r][q] += g[r]*w;
                }
            }
#pragma unroll
            for (int r = 0; r < 4; r++)
#pragma unroll
                for (int q = 0; q < 4; q++) {
                    int i = igrp*4 + r, f = fgrp + 64*q;
                    s.gZ1[i*260 + f] = acc[r][q] * gelu_bwd_f(s.Z1[i*260 + f]);
                }
        }
        __syncthreads();

        // ---- phase 5: X2b = gelu(xq@W1 + b1 - A1e@gZ1)  (into Z1 buffer) ----
        {
            float acc[4][4];
            float4 bb = *(const float4*)&s.b1[f0];
#pragma unroll
            for (int r = 0; r < 4; r++) {
                acc[r][0]=bb.x; acc[r][1]=bb.y; acc[r][2]=bb.z; acc[r][3]=bb.w;
            }
#pragma unroll 8
            for (int d = 0; d < 64; d++) {
                float4 w = *(const float4*)&s.W1[d*256 + f0];
#pragma unroll
                for (int r = 0; r < 4; r++) {
                    float a = s.xq[(igrp*4+r)*65 + d];
                    acc[r][0] += a*w.x; acc[r][1] += a*w.y;
                    acc[r][2] += a*w.z; acc[r][3] += a*w.w;
                }
            }
#pragma unroll
            for (int j = 0; j < 16; j++) {
                float4 g = *(const float4*)&s.gZ1[j*260 + f0];
#pragma unroll
                for (int r = 0; r < 4; r++) {
                    float cf = s.A1e[(igrp*4+r)*16 + j];
                    acc[r][0] -= cf*g.x; acc[r][1] -= cf*g.y;
                    acc[r][2] -= cf*g.z; acc[r][3] -= cf*g.w;
                }
            }
#pragma unroll
            for (int r = 0; r < 4; r++) {
                int i = igrp*4 + r;
                float4 g = make_float4(gelu_f(acc[r][0]), gelu_f(acc[r][1]),
                                       gelu_f(acc[r][2]), gelu_f(acc[r][3]));
                *(float4*)&s.Z1[i*260 + f0] = g;   // X2_bar
            }
        }
        __syncthreads();

        // ---- phase 6: A2e[i][j] = tok[i]*lr[j]*(X2b_i . X2_j + 1)  (j<=i) ----
        {
            int i = tid >> 4, j = tid & 15;
            float acc = 0.0f;
#pragma unroll 8
            for (int f = 0; f < 256; f++) acc += s.Z1[i*260+f] * s.X2[j*260+f];
            s.A2e[tid] = (j <= i) ? s.tok[i]*s.lr[j]*(acc + 1.0f) : 0.0f;
        }
        __syncthreads();

        // ---- phase 7: Z2b = X2b@W2 + b2 - A2e@gZ2 ----
        {
            int ii = tid >> 6, d = tid & 63;
            float bv = s.b2[d];
            float acc[4] = {bv, bv, bv, bv};
#pragma unroll 4
            for (int f = 0; f < 256; f++) {
                float w = s.W2[f*65 + d];
#pragma unroll
                for (int r = 0; r < 4; r++) acc[r] += s.Z1[(ii+4*r)*260 + f] * w;
            }
#pragma unroll
            for (int j = 0; j < 16; j++) {
                float g = s.gZ2[j*65 + d];
#pragma unroll
                for (int r = 0; r < 4; r++) acc[r] -= s.A2e[(ii+4*r)*16 + j] * g;
            }
#pragma unroll
            for (int r = 0; r < 4; r++) s.Z2b[(ii+4*r)*65 + d] = acc[r];
        }
        __syncthreads();

        // ---- phase 8: out = xq + ln_fwd(Z2b)  -> global ----
        for (int rr = 0; rr < 2; rr++) {
            int i = wi*2 + rr;
            float z0 = s.Z2b[i*65+lane], z1 = s.Z2b[i*65+lane+32];
            float mu = warp_sum(z0 + z1) * (1.0f/64.0f);
            float d0 = z0 - mu, d1 = z1 - mu;
            float var = warp_sum(d0*d0 + d1*d1) * (1.0f/64.0f);
            float rstd = rsqrtf(var + EPSV);
            float y0 = s.lnw[lane   ]*d0*rstd + s.lnb[lane   ] + s.xq[i*65+lane];
            float y1 = s.lnw[lane+32]*d1*rstd + s.lnb[lane+32] + s.xq[i*65+lane+32];
            size_t ob = ((size_t)b*NLL + n*CK + i)*NCOLS + h*HDIM;
            g_XQW[ob + lane]      = y0;
            g_XQW[ob + lane + 32] = y1;
        }

        // ---- phase 9: state updates ----
        {
            // b1
            float a = s.b1[tid];
#pragma unroll
            for (int j = 0; j < 16; j++) a -= s.le[j] * s.gZ1[j*260 + tid];
            s.b1[tid] = a;
            // b2
            if (tid < 64) {
                float a2 = s.b2[tid];
#pragma unroll
                for (int j = 0; j < 16; j++) a2 -= s.le[j] * s.gZ2[j*65 + tid];
                s.b2[tid] = a2;
            }
            // W1[d][f] -= sum_j le[j]*xk[j][d]*gZ1[j][f]
            {
                int dgrp = tid >> 6;
#pragma unroll 2
                for (int kk = 0; kk < 16; kk++) {
                    int d = dgrp*16 + kk;
                    float4 w = *(float4*)&s.W1[d*256 + f0];
#pragma unroll
                    for (int j = 0; j < 16; j++) {
                        float c = s.le[j] * s.xk[j*65 + d];
                        float4 g = *(const float4*)&s.gZ1[j*260 + f0];
                        w.x -= c*g.x; w.y -= c*g.y; w.z -= c*g.z; w.w -= c*g.w;
                    }
                    *(float4*)&s.W1[d*256 + f0] = w;
                }
            }
            // W2[f][d] -= sum_j le[j]*X2[j][f]*gZ2[j][d]
            {
                int d = tid & 63, fg = tid >> 6;
                float eg[16];
#pragma unroll
                for (int j = 0; j < 16; j++) eg[j] = s.le[j] * s.gZ2[j*65 + d];
#pragma unroll 4
                for (int kk = 0; kk < 64; kk++) {
                    int f = fg*64 + kk;
                    float w = s.W2[f*65 + d];
#pragma unroll
                    for (int j = 0; j < 16; j++) w -= s.X2[j*260 + f] * eg[j];
                    s.W2[f*65 + d] = w;
                }
            }
        }
        __syncthreads();
    }
}

// ---------------------------------------------------------------------------
// K4: post layer-norm over C=1024
// ---------------------------------------------------------------------------
__global__ void __launch_bounds__(256) postln_kernel(
    const float* __restrict__ pw, const float* __restrict__ pb)
{
    __shared__ float s1[8], s2[8];
    int row = blockIdx.x, tid = threadIdx.x;
    const float4* x4 = (const float4*)(g_XQW + (size_t)row * NCOLS);
    float4 a = x4[tid];
    float sum = a.x + a.y + a.z + a.w;
    float sq  = a.x*a.x + a.y*a.y + a.z*a.z + a.w*a.w;
    sum = warp_sum(sum);
    sq  = warp_sum(sq);
    if ((tid & 31) == 0) { s1[tid>>5] = sum; s2[tid>>5] = sq; }
    __syncthreads();
    float ts = 0.0f, tq = 0.0f;
#pragma unroll
    for (int i = 0; i < 8; i++) { ts += s1[i]; tq += s2[i]; }
    float mu = ts * (1.0f/1024.0f);
    float var = tq * (1.0f/1024.0f) - mu*mu;
    float rstd = rsqrtf(var + EPSV);
    int c = tid * 4;
    float* o = g_norm + (size_t)row * NCOLS + c;
    o[0] = pw[c+0]*(a.x - mu)*rstd + pb[c+0];
    o[1] = pw[c+1]*(a.y - mu)*rstd + pb[c+1];
    o[2] = pw[c+2]*(a.z - mu)*rstd + pb[c+2];
    o[3] = pw[c+3]*(a.w - mu)*rstd + pb[c+3];
}

// ---------------------------------------------------------------------------
// K5: out = g_norm @ wo.T
// ---------------------------------------------------------------------------
__global__ void __launch_bounds__(256) ogemm_kernel(
    const float* __restrict__ wo, float* __restrict__ out)
{
    __shared__ float As[16][68];
    __shared__ float Bs[16][68];

    const int mT = blockIdx.y * 64;
    const int nT = blockIdx.x * 64;
    const int tid = threadIdx.x;

    const int ldr = tid >> 2;
    const int ldc = (tid & 3) * 4;
    const float* Ap = g_norm + (size_t)(mT + ldr) * NCOLS + ldc;
    const float* Bp = wo     + (size_t)(nT + ldr) * NCOLS + ldc;

    const int r0 = (tid >> 4) * 4;
    const int c0 = (tid & 15) * 4;

    float acc[4][4];
#pragma unroll
    for (int r = 0; r < 4; r++)
#pragma unroll
        for (int c = 0; c < 4; c++) acc[r][c] = 0.0f;

    for (int kt = 0; kt < 64; kt++) {
        float4 a = *(const float4*)(Ap + kt * 16);
        float4 b = *(const float4*)(Bp + kt * 16);
        As[ldc+0][ldr] = a.x; As[ldc+1][ldr] = a.y;
        As[ldc+2][ldr] = a.z; As[ldc+3][ldr] = a.w;
        Bs[ldc+0][ldr] = b.x; Bs[ldc+1][ldr] = b.y;
        Bs[ldc+2][ldr] = b.z; Bs[ldc+3][ldr] = b.w;
        __syncthreads();
#pragma unroll
        for (int kk = 0; kk < 16; kk++) {
            float4 av = *(const float4*)&As[kk][r0];
            float4 bv = *(const float4*)&Bs[kk][c0];
            float ar[4] = {av.x, av.y, av.z, av.w};
            float br[4] = {bv.x, bv.y, bv.z, bv.w};
#pragma unroll
            for (int r = 0; r < 4; r++)
#pragma unroll
                for (int c = 0; c < 4; c++) acc[r][c] += ar[r] * br[c];
        }
        __syncthreads();
    }

#pragma unroll
    for (int rr = 0; rr < 4; rr++) {
        size_t m = mT + r0 + rr;
        float4 v = make_float4(acc[rr][0], acc[rr][1], acc[rr][2], acc[rr][3]);
        *(float4*)&out[m * NCOLS + nT + c0] = v;
    }
}

// ---------------------------------------------------------------------------
extern "C" void kernel_launch(void* const* d_in, const int* in_sizes, int n_in,
                              void* d_out, int out_size)
{
    (void)in_sizes; (void)n_in; (void)out_size;
    const float* hs   = (const float*)d_in[0];
    const float* wq   = (const float*)d_in[1];
    const float* wk   = (const float*)d_in[2];
    const float* wv   = (const float*)d_in[3];
    const float* wo   = (const float*)d_in[4];
    const float* lti  = (const float*)d_in[5];
    const float* lrw  = (const float*)d_in[6];
    const float* lrb  = (const float*)d_in[7];
    const float* lnw  = (const float*)d_in[8];
    const float* lnb  = (const float*)d_in[9];
    const float* pnw  = (const float*)d_in[10];
    const float* pnb  = (const float*)d_in[11];
    const float* W1   = (const float*)d_in[12];
    const float* b1   = (const float*)d_in[13];
    const float* W2   = (const float*)d_in[14];
    const float* b2   = (const float*)d_in[15];
    float* out = (float*)d_out;

    cudaFuncSetAttribute(scan_kernel,
                         cudaFuncAttributeMaxDynamicSharedMemorySize,
                         (int)sizeof(ScanSmem));

    qkv_kernel<<<dim3(16, 128, 3), 256>>>(hs, wq, wk, wv);
    lr_kernel<<<NB * NLL, 256>>>(hs, lrw, lrb);
    scan_kernel<<<NB * NHEAD, 256, sizeof(ScanSmem)>>>(W1, b1, W2, b2, lnw, lnb, lti);
    postln_kernel<<<NB * NLL, 256>>>(pnw, pnb);
    ogemm_kernel<<<dim3(16, 128), 256>>>(wo, out);
}

// round 3
// speedup vs baseline: 1.0003x; 1.0003x over previous
#include <cuda_runtime.h>
#include <math.h>

#define NB    4
#define NLL   2048
#define NCOLS 1024
#define NHEAD 16
#define HDIM  64
#define CK    16
#define NCH   128
#define F4C   256
#define EPSV  1e-6f

// ---------------------------------------------------------------------------
// Device-global scratch (allocation-free per harness rules)
// ---------------------------------------------------------------------------
__device__ float g_XQ[NB*NHEAD*NCH*CK*HDIM];
__device__ float g_XK[NB*NHEAD*NCH*CK*HDIM];
__device__ float g_XV[NB*NHEAD*NCH*CK*HDIM];
__device__ float g_lr[NB*NHEAD*NCH*CK];
__device__ float g_XQW[NB*NLL*NCOLS];
__device__ float g_norm[NB*NLL*NCOLS];

// ---------------------------------------------------------------------------
__device__ __forceinline__ float warp_sum(float v) {
#pragma unroll
    for (int o = 16; o > 0; o >>= 1) v += __shfl_xor_sync(0xffffffffu, v, o);
    return v;
}

__device__ __forceinline__ float tanh_fast(float x) {
    float e = __expf(2.0f * x);
    return (e - 1.0f) / (e + 1.0f);
}
__device__ __forceinline__ float gelu_f(float x) {
    float t = tanh_fast(0.79788456f * x * (1.0f + 0.044715f * x * x));
    return 0.5f * x * (1.0f + t);
}
__device__ __forceinline__ float gelu_bwd_f(float x) {
    float t = tanh_fast(0.79788456f * x * (1.0f + 0.044715f * x * x));
    return 0.5f * x * ((1.0f - t * t) * (0.79788456f + 0.1070322243f * x * x))
         + 0.5f * (1.0f + t);
}

// ---------------------------------------------------------------------------
// K1: QKV projection GEMM + RoPE + scatter.  out[m][n] = dot(hs[m], W[n])
// grid (16, 128, 3), 256 thr, 64x64 tile, 4x4 microtile
// ---------------------------------------------------------------------------
__global__ void __launch_bounds__(256) qkv_kernel(
    const float* __restrict__ hs,
    const float* __restrict__ wq,
    const float* __restrict__ wk,
    const float* __restrict__ wv)
{
    __shared__ float As[16][68];
    __shared__ float Bs[16][68];

    const int z = blockIdx.z;
    const float* W = (z == 0) ? wq : ((z == 1) ? wk : wv);
    float* dst = (z == 0) ? g_XQ : ((z == 1) ? g_XK : g_XV);

    const int mT = blockIdx.y * 64;
    const int nT = blockIdx.x * 64;
    const int tid = threadIdx.x;

    const int ldr = tid >> 2;          // 0..63
    const int ldc = (tid & 3) * 4;     // 0,4,8,12
    const float* Ap = hs + (size_t)(mT + ldr) * NCOLS + ldc;
    const float* Bp = W  + (size_t)(nT + ldr) * NCOLS + ldc;

    const int r0 = (tid >> 4) * 4;
    const int c0 = (tid & 15) * 4;

    float acc[4][4];
#pragma unroll
    for (int r = 0; r < 4; r++)
#pragma unroll
        for (int c = 0; c < 4; c++) acc[r][c] = 0.0f;

    for (int kt = 0; kt < 64; kt++) {
        float4 a = *(const float4*)(Ap + kt * 16);
        float4 b = *(const float4*)(Bp + kt * 16);
        As[ldc+0][ldr] = a.x; As[ldc+1][ldr] = a.y;
        As[ldc+2][ldr] = a.z; As[ldc+3][ldr] = a.w;
        Bs[ldc+0][ldr] = b.x; Bs[ldc+1][ldr] = b.y;
        Bs[ldc+2][ldr] = b.z; Bs[ldc+3][ldr] = b.w;
        __syncthreads();
#pragma unroll
        for (int kk = 0; kk < 16; kk++) {
            float4 av = *(const float4*)&As[kk][r0];
            float4 bv = *(const float4*)&Bs[kk][c0];
            float ar[4] = {av.x, av.y, av.z, av.w};
            float br[4] = {bv.x, bv.y, bv.z, bv.w};
#pragma unroll
            for (int r = 0; r < 4; r++)
#pragma unroll
                for (int c = 0; c < 4; c++) acc[r][c] += ar[r] * br[c];
        }
        __syncthreads();
    }

    // Epilogue: RoPE (q,k) + scatter to [bh][n][k][d]
#pragma unroll
    for (int rr = 0; rr < 4; rr++) {
        int m   = mT + r0 + rr;
        int pos = m & 15;
        int bb  = m >> 11;
        int l   = m & 2047;
        int nch = l >> 4;
        int kk  = l & 15;
#pragma unroll
        for (int p = 0; p < 2; p++) {
            int n0 = nT + c0 + 2 * p;
            int h  = n0 >> 6;
            int d  = n0 & 63;
            float x0 = acc[rr][2*p], x1 = acc[rr][2*p+1];
            size_t base = ((((size_t)(bb*NHEAD + h))*NCH + nch)*CK + kk)*HDIM + d;
            if (z < 2) {
                float ang = (float)pos * powf(10000.0f, -((float)d) * (1.0f/64.0f));
                float sn, cs;
                sincosf(ang, &sn, &cs);
                dst[base]   = x0 * cs - x1 * sn;
                dst[base+1] = x0 * sn + x1 * cs;
            } else {
                dst[base]   = x0;
                dst[base+1] = x1;
            }
        }
    }
}

// ---------------------------------------------------------------------------
// K2: ttt_lr = sigmoid(hs . lrw[h] + lrb[h]) / HD    grid 8192, 256 thr
// ---------------------------------------------------------------------------
__global__ void __launch_bounds__(256) lr_kernel(
    const float* __restrict__ hs,
    const float* __restrict__ lrw,
    const float* __restrict__ lrb)
{
    int row = blockIdx.x;
    int w = threadIdx.x >> 5, lane = threadIdx.x & 31;
    const float4* x4 = (const float4*)(hs + (size_t)row * NCOLS);
    for (int h = w; h < NHEAD; h += 8) {
        const float4* w4 = (const float4*)(lrw + (size_t)h * NCOLS);
        float acc = 0.0f;
        for (int c = lane; c < 256; c += 32) {
            float4 a = x4[c], b = w4[c];
            acc += a.x*b.x + a.y*b.y + a.z*b.z + a.w*b.w;
        }
        acc = warp_sum(acc);
        if (lane == 0) {
            float v = 1.0f / (1.0f + __expf(-(acc + lrb[h])));
            int b = row >> 11, l = row & 2047, n = l >> 4, k = l & 15;
            g_lr[(((size_t)(b*NHEAD + h))*NCH + n)*CK + k] = v * (1.0f/64.0f);
        }
    }
}

// ---------------------------------------------------------------------------
// K3: the sequential TTT scan.  One CTA per (b,h), state in smem.
// ---------------------------------------------------------------------------
struct ScanSmem {
    float W1[64*256];    // [d][f]
    float W2[256*65];    // [f][d] pad 65
    float b1[256];
    float b2[64];
    float xq[16*65];
    float xk[16*65];
    float tg[16*65];     // xv - xk
    float Z1[16*260];    // raw Z1, later reused as X2_bar
    float X2[16*260];
    float gZ1[16*260];
    float Z2[16*65];
    float gZ2[16*65];
    float Z2b[16*65];
    float A1e[256];
    float A2e[256];
    float lr[16];
    float le[16];        // last_eta
    float tok[16];
    float lnw[64];
    float lnb[64];
};

__global__ void __launch_bounds__(256, 1) scan_kernel(
    const float* __restrict__ W1g, const float* __restrict__ b1g,
    const float* __restrict__ W2g, const float* __restrict__ b2g,
    const float* __restrict__ lnwg, const float* __restrict__ lnbg,
    const float* __restrict__ ltig)
{
    extern __shared__ float smraw[];
    ScanSmem& s = *reinterpret_cast<ScanSmem*>(smraw);

    const int tid = threadIdx.x;
    const int bh  = blockIdx.x;
    const int b   = bh >> 4;
    const int h   = bh & 15;

    // ---- init state ----
    for (int i = tid; i < 16384; i += 256) s.W1[i] = W1g[(size_t)h*16384 + i];
    for (int i = tid; i < 16384; i += 256) {
        int f = i >> 6, d = i & 63;
        s.W2[f*65 + d] = W2g[(size_t)h*16384 + i];
    }
    s.b1[tid] = b1g[h*256 + tid];
    if (tid < 64) {
        s.b2[tid]  = b2g[h*64 + tid];
        s.lnw[tid] = lnwg[h*64 + tid];
        s.lnb[tid] = lnbg[h*64 + tid];
    }
    if (tid < 16) s.tok[tid] = fmaxf(1.0f/(float)(tid+1) + ltig[tid], 0.0f);
    __syncthreads();

    const int igrp = tid >> 6;        // 0..3
    const int fgrp = tid & 63;        // 0..63
    const int f0   = fgrp << 2;
    const int wi   = tid >> 5;        // warp 0..7
    const int lane = tid & 31;

    for (int n = 0; n < NCH; n++) {
        // ---- phase 0a: load chunk ----
        const float* pq = g_XQ + ((size_t)bh*NCH + n)*1024;
        const float* pk = g_XK + ((size_t)bh*NCH + n)*1024;
        const float* pv = g_XV + ((size_t)bh*NCH + n)*1024;
        for (int idx = tid; idx < 1024; idx += 256) {
            int k = idx >> 6, d = idx & 63;
            float kv = pk[idx];
            s.xq[k*65+d] = pq[idx];
            s.xk[k*65+d] = kv;
            s.tg[k*65+d] = pv[idx] - kv;
        }
        if (tid < 16) {
            float v = g_lr[((size_t)bh*NCH + n)*CK + tid];
            s.lr[tid] = v;
            s.le[tid] = s.tok[15] * v;
        }
        __syncthreads();

        // ---- phase 0b: A1e[i][j] = tok[i]*lr[j]*(xq_i . xk_j + 1)  (j<=i) ----
        {
            int i = tid >> 4, j = tid & 15;
            float acc = 0.0f;
#pragma unroll 16
            for (int d = 0; d < 64; d++) acc += s.xq[i*65+d] * s.xk[j*65+d];
            s.A1e[tid] = (j <= i) ? s.tok[i]*s.lr[j]*(acc + 1.0f) : 0.0f;
        }

        // ---- phase 1: Z1 = xk@W1 + b1 ; X2 = gelu(Z1) ----
        {
            float acc[4][4];
            float4 bb = *(const float4*)&s.b1[f0];
#pragma unroll
            for (int r = 0; r < 4; r++) {
                acc[r][0]=bb.x; acc[r][1]=bb.y; acc[r][2]=bb.z; acc[r][3]=bb.w;
            }
#pragma unroll 8
            for (int d = 0; d < 64; d++) {
                float4 w = *(const float4*)&s.W1[d*256 + f0];
#pragma unroll
                for (int r = 0; r < 4; r++) {
                    float a = s.xk[(igrp*4+r)*65 + d];
                    acc[r][0] += a*w.x; acc[r][1] += a*w.y;
                    acc[r][2] += a*w.z; acc[r][3] += a*w.w;
                }
            }
#pragma unroll
            for (int r = 0; r < 4; r++) {
                int i = igrp*4 + r;
                float4 z = make_float4(acc[r][0], acc[r][1], acc[r][2], acc[r][3]);
                *(float4*)&s.Z1[i*260 + f0] = z;
                float4 g = make_float4(gelu_f(z.x), gelu_f(z.y), gelu_f(z.z), gelu_f(z.w));
                *(float4*)&s.X2[i*260 + f0] = g;
            }
        }
        __syncthreads();

        // ---- phase 2: Z2 = X2@W2 + b2 ----
        {
            int ii = tid >> 6, d = tid & 63;
            float bv = s.b2[d];
            float acc[4] = {bv, bv, bv, bv};
#pragma unroll 4
            for (int f = 0; f < 256; f++) {
                float w = s.W2[f*65 + d];
#pragma unroll
                for (int r = 0; r < 4; r++) acc[r] += s.X2[(ii+4*r)*260 + f] * w;
            }
#pragma unroll
            for (int r = 0; r < 4; r++) s.Z2[(ii+4*r)*65 + d] = acc[r];
        }
        __syncthreads();

        // ---- phase 3: gZ2 = ln_fused_l2_bwd(Z2, tgt) ----
        for (int rr = 0; rr < 2; rr++) {
            int i = wi*2 + rr;
            float z0 = s.Z2[i*65 + lane], z1 = s.Z2[i*65 + lane + 32];
            float mu = warp_sum(z0 + z1) * (1.0f/64.0f);
            float d0 = z0 - mu, d1 = z1 - mu;
            float var = warp_sum(d0*d0 + d1*d1) * (1.0f/64.0f);
            float rstd = rsqrtf(var + EPSV);
            float xh0 = d0*rstd, xh1 = d1*rstd;
            float w0 = s.lnw[lane], w1 = s.lnw[lane+32];
            float go0 = (w0*xh0 + s.lnb[lane]    - s.tg[i*65+lane   ]) * w0;
            float go1 = (w1*xh1 + s.lnb[lane+32] - s.tg[i*65+lane+32]) * w1;
            float sgo = warp_sum(go0 + go1);
            float sgx = warp_sum(go0*xh0 + go1*xh1);
            float sc = rstd * (1.0f/64.0f);
            s.gZ2[i*65+lane]    = (64.0f*go0 - sgo - xh0*sgx) * sc;
            s.gZ2[i*65+lane+32] = (64.0f*go1 - sgo - xh1*sgx) * sc;
        }
        __syncthreads();

        // ---- phase 4: gZ1 = (gZ2 @ W2^T) * gelu_bwd(Z1) ----
        {
            float acc[4][4];
#pragma unroll
            for (int r = 0; r < 4; r++)
#pragma unroll
                for (int q = 0; q < 4; q++) acc[r][q] = 0.0f;
#pragma unroll 4
            for (int d = 0; d < 64; d++) {
                float g[4];
#pragma unroll
                for (int r = 0; r < 4; r++) g[r] = s.gZ2[(igrp*4+r)*65 + d];
#pragma unroll
                for (int q = 0; q < 4; q++) {
                    float w = s.W2[(fgrp + 64*q)*65 + d];
#pragma unroll
                    for (int r = 0; r < 4; r++) acc[r][q] += g[r]*w;
                }
            }
#pragma unroll
            for (int r = 0; r < 4; r++)
#pragma unroll
                for (int q = 0; q < 4; q++) {
                    int i = igrp*4 + r, f = fgrp + 64*q;
                    s.gZ1[i*260 + f] = acc[r][q] * gelu_bwd_f(s.Z1[i*260 + f]);
                }
        }
        __syncthreads();

        // ---- phase 5: X2b = gelu(xq@W1 + b1 - A1e@gZ1)  (into Z1 buffer) ----
        {
            float acc[4][4];
            float4 bb = *(const float4*)&s.b1[f0];
#pragma unroll
            for (int r = 0; r < 4; r++) {
                acc[r][0]=bb.x; acc[r][1]=bb.y; acc[r][2]=bb.z; acc[r][3]=bb.w;
            }
#pragma unroll 8
            for (int d = 0; d < 64; d++) {
                float4 w = *(const float4*)&s.W1[d*256 + f0];
#pragma unroll
                for (int r = 0; r < 4; r++) {
                    float a = s.xq[(igrp*4+r)*65 + d];
                    acc[r][0] += a*w.x; acc[r][1] += a*w.y;
                    acc[r][2] += a*w.z; acc[r][3] += a*w.w;
                }
            }
#pragma unroll
            for (int j = 0; j < 16; j++) {
                float4 g = *(const float4*)&s.gZ1[j*260 + f0];
#pragma unroll
                for (int r = 0; r < 4; r++) {
                    float cf = s.A1e[(igrp*4+r)*16 + j];
                    acc[r][0] -= cf*g.x; acc[r][1] -= cf*g.y;
                    acc[r][2] -= cf*g.z; acc[r][3] -= cf*g.w;
                }
            }
#pragma unroll
            for (int r = 0; r < 4; r++) {
                int i = igrp*4 + r;
                float4 g = make_float4(gelu_f(acc[r][0]), gelu_f(acc[r][1]),
                                       gelu_f(acc[r][2]), gelu_f(acc[r][3]));
                *(float4*)&s.Z1[i*260 + f0] = g;   // X2_bar
            }
        }
        __syncthreads();

        // ---- phase 6: A2e[i][j] = tok[i]*lr[j]*(X2b_i . X2_j + 1)  (j<=i) ----
        {
            int i = tid >> 4, j = tid & 15;
            float acc = 0.0f;
#pragma unroll 8
            for (int f = 0; f < 256; f++) acc += s.Z1[i*260+f] * s.X2[j*260+f];
            s.A2e[tid] = (j <= i) ? s.tok[i]*s.lr[j]*(acc + 1.0f) : 0.0f;
        }
        __syncthreads();

        // ---- phase 7: Z2b = X2b@W2 + b2 - A2e@gZ2 ----
        {
            int ii = tid >> 6, d = tid & 63;
            float bv = s.b2[d];
            float acc[4] = {bv, bv, bv, bv};
#pragma unroll 4
            for (int f = 0; f < 256; f++) {
                float w = s.W2[f*65 + d];
#pragma unroll
                for (int r = 0; r < 4; r++) acc[r] += s.Z1[(ii+4*r)*260 + f] * w;
            }
#pragma unroll
            for (int j = 0; j < 16; j++) {
                float g = s.gZ2[j*65 + d];
#pragma unroll
                for (int r = 0; r < 4; r++) acc[r] -= s.A2e[(ii+4*r)*16 + j] * g;
            }
#pragma unroll
            for (int r = 0; r < 4; r++) s.Z2b[(ii+4*r)*65 + d] = acc[r];
        }
        __syncthreads();

        // ---- phase 8: out = xq + ln_fwd(Z2b)  -> global ----
        for (int rr = 0; rr < 2; rr++) {
            int i = wi*2 + rr;
            float z0 = s.Z2b[i*65+lane], z1 = s.Z2b[i*65+lane+32];
            float mu = warp_sum(z0 + z1) * (1.0f/64.0f);
            float d0 = z0 - mu, d1 = z1 - mu;
            float var = warp_sum(d0*d0 + d1*d1) * (1.0f/64.0f);
            float rstd = rsqrtf(var + EPSV);
            float y0 = s.lnw[lane   ]*d0*rstd + s.lnb[lane   ] + s.xq[i*65+lane];
            float y1 = s.lnw[lane+32]*d1*rstd + s.lnb[lane+32] + s.xq[i*65+lane+32];
            size_t ob = ((size_t)b*NLL + n*CK + i)*NCOLS + h*HDIM;
            g_XQW[ob + lane]      = y0;
            g_XQW[ob + lane + 32] = y1;
        }

        // ---- phase 9: state updates ----
        {
            // b1
            float a = s.b1[tid];
#pragma unroll
            for (int j = 0; j < 16; j++) a -= s.le[j] * s.gZ1[j*260 + tid];
            s.b1[tid] = a;
            // b2
            if (tid < 64) {
                float a2 = s.b2[tid];
#pragma unroll
                for (int j = 0; j < 16; j++) a2 -= s.le[j] * s.gZ2[j*65 + tid];
                s.b2[tid] = a2;
            }
            // W1[d][f] -= sum_j le[j]*xk[j][d]*gZ1[j][f]
            {
                int dgrp = tid >> 6;
#pragma unroll 2
                for (int kk = 0; kk < 16; kk++) {
                    int d = dgrp*16 + kk;
                    float4 w = *(float4*)&s.W1[d*256 + f0];
#pragma unroll
                    for (int j = 0; j < 16; j++) {
                        float c = s.le[j] * s.xk[j*65 + d];
                        float4 g = *(const float4*)&s.gZ1[j*260 + f0];
                        w.x -= c*g.x; w.y -= c*g.y; w.z -= c*g.z; w.w -= c*g.w;
                    }
                    *(float4*)&s.W1[d*256 + f0] = w;
                }
            }
            // W2[f][d] -= sum_j le[j]*X2[j][f]*gZ2[j][d]
            {
                int d = tid & 63, fg = tid >> 6;
                float eg[16];
#pragma unroll
                for (int j = 0; j < 16; j++) eg[j] = s.le[j] * s.gZ2[j*65 + d];
#pragma unroll 4
                for (int kk = 0; kk < 64; kk++) {
                    int f = fg*64 + kk;
                    float w = s.W2[f*65 + d];
#pragma unroll
                    for (int j = 0; j < 16; j++) w -= s.X2[j*260 + f] * eg[j];
                    s.W2[f*65 + d] = w;
                }
            }
        }
        __syncthreads();
    }
}

// ---------------------------------------------------------------------------
// K4: post layer-norm over C=1024
// ---------------------------------------------------------------------------
__global__ void __launch_bounds__(256) postln_kernel(
    const float* __restrict__ pw, const float* __restrict__ pb)
{
    __shared__ float s1[8], s2[8];
    int row = blockIdx.x, tid = threadIdx.x;
    const float4* x4 = (const float4*)(g_XQW + (size_t)row * NCOLS);
    float4 a = x4[tid];
    float sum = a.x + a.y + a.z + a.w;
    float sq  = a.x*a.x + a.y*a.y + a.z*a.z + a.w*a.w;
    sum = warp_sum(sum);
    sq  = warp_sum(sq);
    if ((tid & 31) == 0) { s1[tid>>5] = sum; s2[tid>>5] = sq; }
    __syncthreads();
    float ts = 0.0f, tq = 0.0f;
#pragma unroll
    for (int i = 0; i < 8; i++) { ts += s1[i]; tq += s2[i]; }
    float mu = ts * (1.0f/1024.0f);
    float var = tq * (1.0f/1024.0f) - mu*mu;
    float rstd = rsqrtf(var + EPSV);
    int c = tid * 4;
    float* o = g_norm + (size_t)row * NCOLS + c;
    o[0] = pw[c+0]*(a.x - mu)*rstd + pb[c+0];
    o[1] = pw[c+1]*(a.y - mu)*rstd + pb[c+1];
    o[2] = pw[c+2]*(a.z - mu)*rstd + pb[c+2];
    o[3] = pw[c+3]*(a.w - mu)*rstd + pb[c+3];
}

// ---------------------------------------------------------------------------
// K5: out = g_norm @ wo.T
// ---------------------------------------------------------------------------
__global__ void __launch_bounds__(256) ogemm_kernel(
    const float* __restrict__ wo, float* __restrict__ out)
{
    __shared__ float As[16][68];
    __shared__ float Bs[16][68];

    const int mT = blockIdx.y * 64;
    const int nT = blockIdx.x * 64;
    const int tid = threadIdx.x;

    const int ldr = tid >> 2;
    const int ldc = (tid & 3) * 4;
    const float* Ap = g_norm + (size_t)(mT + ldr) * NCOLS + ldc;
    const float* Bp = wo     + (size_t)(nT + ldr) * NCOLS + ldc;

    const int r0 = (tid >> 4) * 4;
    const int c0 = (tid & 15) * 4;

    float acc[4][4];
#pragma unroll
    for (int r = 0; r < 4; r++)
#pragma unroll
        for (int c = 0; c < 4; c++) acc[r][c] = 0.0f;

    for (int kt = 0; kt < 64; kt++) {
        float4 a = *(const float4*)(Ap + kt * 16);
        float4 b = *(const float4*)(Bp + kt * 16);
        As[ldc+0][ldr] = a.x; As[ldc+1][ldr] = a.y;
        As[ldc+2][ldr] = a.z; As[ldc+3][ldr] = a.w;
        Bs[ldc+0][ldr] = b.x; Bs[ldc+1][ldr] = b.y;
        Bs[ldc+2][ldr] = b.z; Bs[ldc+3][ldr] = b.w;
        __syncthreads();
#pragma unroll
        for (int kk = 0; kk < 16; kk++) {
            float4 av = *(const float4*)&As[kk][r0];
            float4 bv = *(const float4*)&Bs[kk][c0];
            float ar[4] = {av.x, av.y, av.z, av.w};
            float br[4] = {bv.x, bv.y, bv.z, bv.w};
#pragma unroll
            for (int r = 0; r < 4; r++)
#pragma unroll
                for (int c = 0; c < 4; c++) acc[r][c] += ar[r] * br[c];
        }
        __syncthreads();
    }

#pragma unroll
    for (int rr = 0; rr < 4; rr++) {
        size_t m = mT + r0 + rr;
        float4 v = make_float4(acc[rr][0], acc[rr][1], acc[rr][2], acc[rr][3]);
        *(float4*)&out[m * NCOLS + nT + c0] = v;
    }
}

// ---------------------------------------------------------------------------
extern "C" void kernel_launch(void* const* d_in, const int* in_sizes, int n_in,
                              void* d_out, int out_size)
{
    (void)in_sizes; (void)n_in; (void)out_size;
    const float* hs   = (const float*)d_in[0];
    const float* wq   = (const float*)d_in[1];
    const float* wk   = (const float*)d_in[2];
    const float* wv   = (const float*)d_in[3];
    const float* wo   = (const float*)d_in[4];
    const float* lti  = (const float*)d_in[5];
    const float* lrw  = (const float*)d_in[6];
    const float* lrb  = (const float*)d_in[7];
    const float* lnw  = (const float*)d_in[8];
    const float* lnb  = (const float*)d_in[9];
    const float* pnw  = (const float*)d_in[10];
    const float* pnb  = (const float*)d_in[11];
    const float* W1   = (const float*)d_in[12];
    const float* b1   = (const float*)d_in[13];
    const float* W2   = (const float*)d_in[14];
    const float* b2   = (const float*)d_in[15];
    float* out = (float*)d_out;

    cudaFuncSetAttribute(scan_kernel,
                         cudaFuncAttributeMaxDynamicSharedMemorySize,
                         (int)sizeof(ScanSmem));

    qkv_kernel<<<dim3(16, 128, 3), 256>>>(hs, wq, wk, wv);
    lr_kernel<<<NB * NLL, 256>>>(hs, lrw, lrb);
    scan_kernel<<<NB * NHEAD, 256, sizeof(ScanSmem)>>>(W1, b1, W2, b2, lnw, lnb, lti);
    postln_kernel<<<NB * NLL, 256>>>(pnw, pnb);
    ogemm_kernel<<<dim3(16, 128), 256>>>(wo, out);
}

// round 4
// speedup vs baseline: 1.3434x; 1.3430x over previous
#include <cuda_runtime.h>
#include <math.h>
#include <stdint.h>

#define NB    4
#define NLL   2048
#define NCOLS 1024
#define NHEAD 16
#define HDIM  64
#define CK    16
#define NCH   128
#define EPSV  1e-6f

__device__ float g_XQ[NB*NHEAD*NCH*CK*HDIM];
__device__ float g_XK[NB*NHEAD*NCH*CK*HDIM];
__device__ float g_XV[NB*NHEAD*NCH*CK*HDIM];
__device__ float g_lr[NB*NHEAD*NCH*CK];
__device__ float g_XQW[NB*NLL*NCOLS];
__device__ float g_norm[NB*NLL*NCOLS];

__device__ __forceinline__ float warp_sum(float v) {
#pragma unroll
    for (int o = 16; o > 0; o >>= 1) v += __shfl_xor_sync(0xffffffffu, v, o);
    return v;
}
__device__ __forceinline__ float tanh_fast(float x) {
    float e = __expf(2.0f * x);
    return (e - 1.0f) / (e + 1.0f);
}
__device__ __forceinline__ float gelu_f(float x) {
    float t = tanh_fast(0.79788456f * x * (1.0f + 0.044715f * x * x));
    return 0.5f * x * (1.0f + t);
}
__device__ __forceinline__ float gelu_bwd_f(float x) {
    float t = tanh_fast(0.79788456f * x * (1.0f + 0.044715f * x * x));
    return 0.5f * x * ((1.0f - t * t) * (0.79788456f + 0.1070322243f * x * x))
         + 0.5f * (1.0f + t);
}
__device__ __forceinline__ uint32_t smem_u32p(const void* p) {
    uint32_t a;
    asm("{.reg .u64 t; cvta.to.shared.u64 t, %1; cvt.u32.u64 %0, t;}" : "=r"(a) : "l"(p));
    return a;
}
__device__ __forceinline__ uint32_t mapa_u32(uint32_t a, uint32_t r) {
    uint32_t o; asm("mapa.shared::cluster.u32 %0, %1, %2;" : "=r"(o) : "r"(a), "r"(r));
    return o;
}
__device__ __forceinline__ float ldc_f32(uint32_t a) {
    float v; asm volatile("ld.shared::cluster.f32 %0, [%1];" : "=f"(v) : "r"(a));
    return v;
}
#define CLUSTER_SYNC() do { \
    asm volatile("barrier.cluster.arrive.aligned;" ::: "memory"); \
    asm volatile("barrier.cluster.wait.aligned;" ::: "memory"); } while (0)

// ---------------------------------------------------------------------------
// K1: QKV GEMM + RoPE + scatter (unchanged from passing baseline)
// ---------------------------------------------------------------------------
__global__ void __launch_bounds__(256) qkv_kernel(
    const float* __restrict__ hs, const float* __restrict__ wq,
    const float* __restrict__ wk, const float* __restrict__ wv)
{
    __shared__ float As[16][68];
    __shared__ float Bs[16][68];
    const int z = blockIdx.z;
    const float* W = (z == 0) ? wq : ((z == 1) ? wk : wv);
    float* dst = (z == 0) ? g_XQ : ((z == 1) ? g_XK : g_XV);
    const int mT = blockIdx.y * 64, nT = blockIdx.x * 64, tid = threadIdx.x;
    const int ldr = tid >> 2, ldc = (tid & 3) * 4;
    const float* Ap = hs + (size_t)(mT + ldr) * NCOLS + ldc;
    const float* Bp = W  + (size_t)(nT + ldr) * NCOLS + ldc;
    const int r0 = (tid >> 4) * 4, c0 = (tid & 15) * 4;
    float acc[4][4];
#pragma unroll
    for (int r = 0; r < 4; r++)
#pragma unroll
        for (int c = 0; c < 4; c++) acc[r][c] = 0.0f;
    for (int kt = 0; kt < 64; kt++) {
        float4 a = *(const float4*)(Ap + kt * 16);
        float4 b = *(const float4*)(Bp + kt * 16);
        As[ldc+0][ldr]=a.x; As[ldc+1][ldr]=a.y; As[ldc+2][ldr]=a.z; As[ldc+3][ldr]=a.w;
        Bs[ldc+0][ldr]=b.x; Bs[ldc+1][ldr]=b.y; Bs[ldc+2][ldr]=b.z; Bs[ldc+3][ldr]=b.w;
        __syncthreads();
#pragma unroll
        for (int kk = 0; kk < 16; kk++) {
            float4 av = *(const float4*)&As[kk][r0];
            float4 bv = *(const float4*)&Bs[kk][c0];
            float ar[4] = {av.x, av.y, av.z, av.w};
            float br[4] = {bv.x, bv.y, bv.z, bv.w};
#pragma unroll
            for (int r = 0; r < 4; r++)
#pragma unroll
                for (int c = 0; c < 4; c++) acc[r][c] += ar[r] * br[c];
        }
        __syncthreads();
    }
#pragma unroll
    for (int rr = 0; rr < 4; rr++) {
        int m = mT + r0 + rr;
        int pos = m & 15, bb = m >> 11, l = m & 2047, nch = l >> 4, kk = l & 15;
#pragma unroll
        for (int p = 0; p < 2; p++) {
            int n0 = nT + c0 + 2 * p, h = n0 >> 6, d = n0 & 63;
            float x0 = acc[rr][2*p], x1 = acc[rr][2*p+1];
            size_t base = ((((size_t)(bb*NHEAD + h))*NCH + nch)*CK + kk)*HDIM + d;
            if (z < 2) {
                float ang = (float)pos * powf(10000.0f, -((float)d) * (1.0f/64.0f));
                float sn, cs; sincosf(ang, &sn, &cs);
                dst[base] = x0*cs - x1*sn; dst[base+1] = x0*sn + x1*cs;
            } else { dst[base] = x0; dst[base+1] = x1; }
        }
    }
}

// ---------------------------------------------------------------------------
// K2: ttt_lr
// ---------------------------------------------------------------------------
__global__ void __launch_bounds__(256) lr_kernel(
    const float* __restrict__ hs, const float* __restrict__ lrw,
    const float* __restrict__ lrb)
{
    int row = blockIdx.x, w = threadIdx.x >> 5, lane = threadIdx.x & 31;
    const float4* x4 = (const float4*)(hs + (size_t)row * NCOLS);
    for (int h = w; h < NHEAD; h += 8) {
        const float4* w4 = (const float4*)(lrw + (size_t)h * NCOLS);
        float acc = 0.0f;
        for (int c = lane; c < 256; c += 32) {
            float4 a = x4[c], b = w4[c];
            acc += a.x*b.x + a.y*b.y + a.z*b.z + a.w*b.w;
        }
        acc = warp_sum(acc);
        if (lane == 0) {
            float v = 1.0f / (1.0f + __expf(-(acc + lrb[h])));
            int b = row >> 11, l = row & 2047, n = l >> 4, k = l & 15;
            g_lr[(((size_t)(b*NHEAD + h))*NCH + n)*CK + k] = v * (1.0f/64.0f);
        }
    }
}

// ---------------------------------------------------------------------------
// K3: cluster-2 f-split TTT scan. grid=128 (64 clusters of 2). rank owns
// f in [rank*128, rank*128+128).
// ---------------------------------------------------------------------------
struct SSm {
    float W1[64*128];     // [d][f_own]
    float W2T[64*132];    // [d][f_own] (W2 transposed)
    float b1h[128], b2[64];
    float xq[16*68], xk[16*68], tg[16*68];
    float Z1[16*132];     // Z1 raw, later X2_bar
    float X2[16*132];
    float gZ1[16*132];
    float gZ2[16*68];
    float Zp[16*68];      // partial Z2 (own half)
    float Z2[16*68];
    float Dp[16*68];      // partial X2b@W2
    float Z2b[16*68];
    float Sp[256];        // partial X2b.X2 dots
    float A1e[256], A2e[256];
    float lr[16], le[16], tok[16];
    float lnw[64], lnb[64];
};

__global__ void __launch_bounds__(256, 1) __cluster_dims__(2, 1, 1)
scan_kernel(const float* __restrict__ W1g, const float* __restrict__ b1g,
            const float* __restrict__ W2g, const float* __restrict__ b2g,
            const float* __restrict__ lnwg, const float* __restrict__ lnbg,
            const float* __restrict__ ltig)
{
    extern __shared__ float smraw[];
    SSm& s = *reinterpret_cast<SSm*>(smraw);
    const int tid = threadIdx.x;
    const int cid = blockIdx.x >> 1;        // (b,h)
    const int rank = blockIdx.x & 1;
    const int b = cid >> 4, h = cid & 15;
    const int foff = rank * 128;
    const uint32_t sbase = smem_u32p(smraw);
    const uint32_t pbase = mapa_u32(sbase, (uint32_t)(rank ^ 1));
    const uint32_t offZp = (uint32_t)((char*)s.Zp - (char*)&s);
    const uint32_t offSp = (uint32_t)((char*)s.Sp - (char*)&s);
    const uint32_t offDp = (uint32_t)((char*)s.Dp - (char*)&s);

    for (int i = tid; i < 8192; i += 256) {
        int d = i >> 7, fl = i & 127;
        s.W1[d*128 + fl] = W1g[(size_t)h*16384 + d*256 + foff + fl];
    }
    for (int i = tid; i < 8192; i += 256) {
        int d = i & 63, fl = i >> 6;
        s.W2T[d*132 + fl] = W2g[(size_t)h*16384 + (size_t)(foff + fl)*64 + d];
    }
    if (tid < 128) s.b1h[tid] = b1g[h*256 + foff + tid];
    if (tid < 64) {
        s.b2[tid] = b2g[h*64 + tid];
        s.lnw[tid] = lnwg[h*64 + tid];
        s.lnb[tid] = lnbg[h*64 + tid];
    }
    if (tid < 16) s.tok[tid] = fmaxf(1.0f/(float)(tid+1) + ltig[tid], 0.0f);
    __syncthreads();

    const int wi = tid >> 5, lane = tid & 31;
    const int i0 = wi * 2;          // row pair for f-mapped phases
    const int f0 = lane * 4;        // own-f column quad

    for (int n = 0; n < NCH; n++) {
        // P0: load chunk
        {
            const float* pq = g_XQ + ((size_t)cid*NCH + n)*1024;
            const float* pk = g_XK + ((size_t)cid*NCH + n)*1024;
            const float* pv = g_XV + ((size_t)cid*NCH + n)*1024;
            int row = tid >> 4, c4 = (tid & 15) * 4;
            float4 q = *(const float4*)(pq + row*64 + c4);
            float4 k = *(const float4*)(pk + row*64 + c4);
            float4 v = *(const float4*)(pv + row*64 + c4);
            *(float4*)&s.xq[row*68 + c4] = q;
            *(float4*)&s.xk[row*68 + c4] = k;
            *(float4*)&s.tg[row*68 + c4] = make_float4(v.x-k.x, v.y-k.y, v.z-k.z, v.w-k.w);
        }
        if (tid < 16) {
            float v = g_lr[((size_t)cid*NCH + n)*CK + tid];
            s.lr[tid] = v;
            s.le[tid] = s.tok[15] * v;
        }
        __syncthreads();

        // P0b: A1e[i][j] = tok[i]*lr[j]*(xq_i.xk_j + 1), j<=i (redundant)
        {
            int i = tid >> 4, j = tid & 15;
            const float4* q4 = (const float4*)&s.xq[i*68];
            const float4* k4 = (const float4*)&s.xk[j*68];
            float acc = 0.0f;
#pragma unroll
            for (int t = 0; t < 16; t++) {
                float4 a = q4[t], c = k4[t];
                acc += a.x*c.x + a.y*c.y + a.z*c.z + a.w*c.w;
            }
            s.A1e[tid] = (j <= i) ? s.tok[i]*s.lr[j]*(acc + 1.0f) : 0.0f;
        }

        // P1: Z1 = xk@W1h + b1h ; X2 = gelu(Z1)
        {
            float4 bb = *(const float4*)&s.b1h[f0];
            float a00=bb.x,a01=bb.y,a02=bb.z,a03=bb.w;
            float a10=bb.x,a11=bb.y,a12=bb.z,a13=bb.w;
#pragma unroll 8
            for (int d = 0; d < 64; d++) {
                float4 w = *(const float4*)&s.W1[d*128 + f0];
                float x0 = s.xk[i0*68 + d], x1 = s.xk[(i0+1)*68 + d];
                a00 += x0*w.x; a01 += x0*w.y; a02 += x0*w.z; a03 += x0*w.w;
                a10 += x1*w.x; a11 += x1*w.y; a12 += x1*w.z; a13 += x1*w.w;
            }
            *(float4*)&s.Z1[i0*132 + f0] = make_float4(a00,a01,a02,a03);
            *(float4*)&s.Z1[(i0+1)*132 + f0] = make_float4(a10,a11,a12,a13);
            *(float4*)&s.X2[i0*132 + f0] =
                make_float4(gelu_f(a00),gelu_f(a01),gelu_f(a02),gelu_f(a03));
            *(float4*)&s.X2[(i0+1)*132 + f0] =
                make_float4(gelu_f(a10),gelu_f(a11),gelu_f(a12),gelu_f(a13));
        }
        __syncthreads();

        // P2: Zp[i][d] = X2_i . W2T[:,d] over own f
        {
            int i = tid >> 4, dq = tid & 15;
            float acc[4] = {0,0,0,0};
            const float4* x4 = (const float4*)&s.X2[i*132];
#pragma unroll 4
            for (int t = 0; t < 32; t++) {
                float4 xv = x4[t];
#pragma unroll
                for (int jd = 0; jd < 4; jd++) {
                    float4 w = *(const float4*)&s.W2T[(dq + 16*jd)*132 + 4*t];
                    acc[jd] += xv.x*w.x + xv.y*w.y + xv.z*w.z + xv.w*w.w;
                }
            }
#pragma unroll
            for (int jd = 0; jd < 4; jd++) s.Zp[i*68 + dq + 16*jd] = acc[jd];
        }
        CLUSTER_SYNC();

        // P2b: Z2 = Zp + peerZp + b2
        {
            int i = tid >> 4, d0 = (tid & 15) * 4;
            float4 own = *(const float4*)&s.Zp[i*68 + d0];
            uint32_t pa = pbase + offZp + (uint32_t)(i*68 + d0) * 4u;
            float4 bb = *(const float4*)&s.b2[d0];
            *(float4*)&s.Z2[i*68 + d0] = make_float4(
                own.x + ldc_f32(pa)    + bb.x, own.y + ldc_f32(pa+4)  + bb.y,
                own.z + ldc_f32(pa+8)  + bb.z, own.w + ldc_f32(pa+12) + bb.w);
        }
        __syncthreads();

        // P3: gZ2 = ln_fused_l2_bwd(Z2, tg)  (redundant)
        for (int rr = 0; rr < 2; rr++) {
            int i = wi*2 + rr;
            float z0 = s.Z2[i*68 + lane], z1 = s.Z2[i*68 + lane + 32];
            float mu = warp_sum(z0 + z1) * (1.0f/64.0f);
            float d0 = z0 - mu, d1 = z1 - mu;
            float var = warp_sum(d0*d0 + d1*d1) * (1.0f/64.0f);
            float rstd = rsqrtf(var + EPSV);
            float xh0 = d0*rstd, xh1 = d1*rstd;
            float w0 = s.lnw[lane], w1 = s.lnw[lane+32];
            float go0 = (w0*xh0 + s.lnb[lane]    - s.tg[i*68+lane   ]) * w0;
            float go1 = (w1*xh1 + s.lnb[lane+32] - s.tg[i*68+lane+32]) * w1;
            float sgo = warp_sum(go0 + go1);
            float sgx = warp_sum(go0*xh0 + go1*xh1);
            float sc = rstd * (1.0f/64.0f);
            s.gZ2[i*68+lane]    = (64.0f*go0 - sgo - xh0*sgx) * sc;
            s.gZ2[i*68+lane+32] = (64.0f*go1 - sgo - xh1*sgx) * sc;
        }
        __syncthreads();

        // P4: gZ1 = (gZ2 @ W2h^T) * gelu_bwd(Z1)
        {
            float a00=0,a01=0,a02=0,a03=0,a10=0,a11=0,a12=0,a13=0;
#pragma unroll 8
            for (int d = 0; d < 64; d++) {
                float4 w = *(const float4*)&s.W2T[d*132 + f0];
                float g0 = s.gZ2[i0*68 + d], g1 = s.gZ2[(i0+1)*68 + d];
                a00 += g0*w.x; a01 += g0*w.y; a02 += g0*w.z; a03 += g0*w.w;
                a10 += g1*w.x; a11 += g1*w.y; a12 += g1*w.z; a13 += g1*w.w;
            }
            float4 z0 = *(const float4*)&s.Z1[i0*132 + f0];
            float4 z1 = *(const float4*)&s.Z1[(i0+1)*132 + f0];
            *(float4*)&s.gZ1[i0*132 + f0] = make_float4(
                a00*gelu_bwd_f(z0.x), a01*gelu_bwd_f(z0.y),
                a02*gelu_bwd_f(z0.z), a03*gelu_bwd_f(z0.w));
            *(float4*)&s.gZ1[(i0+1)*132 + f0] = make_float4(
                a10*gelu_bwd_f(z1.x), a11*gelu_bwd_f(z1.y),
                a12*gelu_bwd_f(z1.z), a13*gelu_bwd_f(z1.w));
        }
        __syncthreads();

        // P5: X2b = gelu(xq@W1h + b1h - A1e@gZ1h) -> Z1 buffer
        {
            float4 bb = *(const float4*)&s.b1h[f0];
            float a00=bb.x,a01=bb.y,a02=bb.z,a03=bb.w;
            float a10=bb.x,a11=bb.y,a12=bb.z,a13=bb.w;
#pragma unroll 8
            for (int d = 0; d < 64; d++) {
                float4 w = *(const float4*)&s.W1[d*128 + f0];
                float x0 = s.xq[i0*68 + d], x1 = s.xq[(i0+1)*68 + d];
                a00 += x0*w.x; a01 += x0*w.y; a02 += x0*w.z; a03 += x0*w.w;
                a10 += x1*w.x; a11 += x1*w.y; a12 += x1*w.z; a13 += x1*w.w;
            }
#pragma unroll
            for (int j = 0; j < 16; j++) {
                float4 g = *(const float4*)&s.gZ1[j*132 + f0];
                float e0 = s.A1e[i0*16 + j], e1 = s.A1e[(i0+1)*16 + j];
                a00 -= e0*g.x; a01 -= e0*g.y; a02 -= e0*g.z; a03 -= e0*g.w;
                a10 -= e1*g.x; a11 -= e1*g.y; a12 -= e1*g.z; a13 -= e1*g.w;
            }
            *(float4*)&s.Z1[i0*132 + f0] =
                make_float4(gelu_f(a00),gelu_f(a01),gelu_f(a02),gelu_f(a03));
            *(float4*)&s.Z1[(i0+1)*132 + f0] =
                make_float4(gelu_f(a10),gelu_f(a11),gelu_f(a12),gelu_f(a13));
        }
        __syncthreads();

        // P6: Sp[i][j] = X2b_i . X2_j (own f)
        {
            int i = tid >> 4, j = tid & 15;
            const float4* x4 = (const float4*)&s.Z1[i*132];
            const float4* y4 = (const float4*)&s.X2[j*132];
            float acc = 0.0f;
#pragma unroll 8
            for (int t = 0; t < 32; t++) {
                float4 a = x4[t], c = y4[t];
                acc += a.x*c.x + a.y*c.y + a.z*c.z + a.w*c.w;
            }
            s.Sp[tid] = acc;
        }
        // P7a: Dp[i][d] = X2b_i @ W2h (own f)
        {
            int i = tid >> 4, dq = tid & 15;
            float acc[4] = {0,0,0,0};
            const float4* x4 = (const float4*)&s.Z1[i*132];
#pragma unroll 4
            for (int t = 0; t < 32; t++) {
                float4 xv = x4[t];
#pragma unroll
                for (int jd = 0; jd < 4; jd++) {
                    float4 w = *(const float4*)&s.W2T[(dq + 16*jd)*132 + 4*t];
                    acc[jd] += xv.x*w.x + xv.y*w.y + xv.z*w.z + xv.w*w.w;
                }
            }
#pragma unroll
            for (int jd = 0; jd < 4; jd++) s.Dp[i*68 + dq + 16*jd] = acc[jd];
        }
        CLUSTER_SYNC();

        // P7b: A2e from summed dots
        {
            int i = tid >> 4, j = tid & 15;
            float sp = s.Sp[tid] + ldc_f32(pbase + offSp + (uint32_t)tid * 4u);
            s.A2e[tid] = (j <= i) ? s.tok[i]*s.lr[j]*(sp + 1.0f) : 0.0f;
        }
        __syncthreads();

        // P7c: Z2b (own 8 rows) = Dp + peerDp + b2 - A2e@gZ2
        {
            int i = rank*8 + wi;
            int d0 = lane * 2;
            uint32_t pa = pbase + offDp + (uint32_t)(i*68 + d0) * 4u;
            float v0 = s.Dp[i*68 + d0]     + ldc_f32(pa)   + s.b2[d0];
            float v1 = s.Dp[i*68 + d0 + 1] + ldc_f32(pa+4) + s.b2[d0+1];
#pragma unroll
            for (int j = 0; j < 16; j++) {
                float a = s.A2e[i*16 + j];
                v0 -= a * s.gZ2[j*68 + d0];
                v1 -= a * s.gZ2[j*68 + d0 + 1];
            }
            s.Z2b[i*68 + d0] = v0;
            s.Z2b[i*68 + d0 + 1] = v1;
        }
        __syncthreads();

        // P8: out = xq + ln_fwd(Z2b)  (own 8 rows)
        {
            int i = rank*8 + wi;
            float z0 = s.Z2b[i*68 + lane], z1 = s.Z2b[i*68 + lane + 32];
            float mu = warp_sum(z0 + z1) * (1.0f/64.0f);
            float d0 = z0 - mu, d1 = z1 - mu;
            float var = warp_sum(d0*d0 + d1*d1) * (1.0f/64.0f);
            float rstd = rsqrtf(var + EPSV);
            float y0 = s.lnw[lane   ]*d0*rstd + s.lnb[lane   ] + s.xq[i*68+lane];
            float y1 = s.lnw[lane+32]*d1*rstd + s.lnb[lane+32] + s.xq[i*68+lane+32];
            size_t ob = ((size_t)b*NLL + (size_t)n*CK + i)*NCOLS + h*HDIM;
            g_XQW[ob + lane] = y0;
            g_XQW[ob + lane + 32] = y1;
        }

        // P9: state updates (own halves; b2 redundant)
        {
#pragma unroll 1
            for (int s8 = 0; s8 < 8; s8++) {
                int d = wi + 8*s8;
                float cj[16], ej[16];
#pragma unroll
                for (int j = 0; j < 16; j++) {
                    cj[j] = s.le[j] * s.xk[j*68 + d];
                    ej[j] = s.le[j] * s.gZ2[j*68 + d];
                }
                float4 w1 = *(const float4*)&s.W1[d*128 + f0];
                float4 w2 = *(const float4*)&s.W2T[d*132 + f0];
#pragma unroll
                for (int j = 0; j < 16; j++) {
                    float4 g = *(const float4*)&s.gZ1[j*132 + f0];
                    float4 x = *(const float4*)&s.X2[j*132 + f0];
                    w1.x -= cj[j]*g.x; w1.y -= cj[j]*g.y;
                    w1.z -= cj[j]*g.z; w1.w -= cj[j]*g.w;
                    w2.x -= ej[j]*x.x; w2.y -= ej[j]*x.y;
                    w2.z -= ej[j]*x.z; w2.w -= ej[j]*x.w;
                }
                *(float4*)&s.W1[d*128 + f0]  = w1;
                *(float4*)&s.W2T[d*132 + f0] = w2;
            }
            if (tid < 128) {
                float a = s.b1h[tid];
#pragma unroll
                for (int j = 0; j < 16; j++) a -= s.le[j] * s.gZ1[j*132 + tid];
                s.b1h[tid] = a;
            }
            if (tid < 64) {
                float a = s.b2[tid];
#pragma unroll
                for (int j = 0; j < 16; j++) a -= s.le[j] * s.gZ2[j*68 + tid];
                s.b2[tid] = a;
            }
        }
        CLUSTER_SYNC();   // fences Zp/Sp/Dp reuse + state update visibility
    }
}

// ---------------------------------------------------------------------------
// K4: post layer-norm
// ---------------------------------------------------------------------------
__global__ void __launch_bounds__(256) postln_kernel(
    const float* __restrict__ pw, const float* __restrict__ pb)
{
    __shared__ float s1[8], s2[8];
    int row = blockIdx.x, tid = threadIdx.x;
    const float4* x4 = (const float4*)(g_XQW + (size_t)row * NCOLS);
    float4 a = x4[tid];
    float sum = a.x + a.y + a.z + a.w;
    float sq  = a.x*a.x + a.y*a.y + a.z*a.z + a.w*a.w;
    sum = warp_sum(sum); sq = warp_sum(sq);
    if ((tid & 31) == 0) { s1[tid>>5] = sum; s2[tid>>5] = sq; }
    __syncthreads();
    float ts = 0.0f, tq = 0.0f;
#pragma unroll
    for (int i = 0; i < 8; i++) { ts += s1[i]; tq += s2[i]; }
    float mu = ts * (1.0f/1024.0f);
    float var = tq * (1.0f/1024.0f) - mu*mu;
    float rstd = rsqrtf(var + EPSV);
    int c = tid * 4;
    float* o = g_norm + (size_t)row * NCOLS + c;
    o[0] = pw[c+0]*(a.x - mu)*rstd + pb[c+0];
    o[1] = pw[c+1]*(a.y - mu)*rstd + pb[c+1];
    o[2] = pw[c+2]*(a.z - mu)*rstd + pb[c+2];
    o[3] = pw[c+3]*(a.w - mu)*rstd + pb[c+3];
}

// ---------------------------------------------------------------------------
// K5: out = g_norm @ wo.T
// ---------------------------------------------------------------------------
__global__ void __launch_bounds__(256) ogemm_kernel(
    const float* __restrict__ wo, float* __restrict__ out)
{
    __shared__ float As[16][68];
    __shared__ float Bs[16][68];
    const int mT = blockIdx.y * 64, nT = blockIdx.x * 64, tid = threadIdx.x;
    const int ldr = tid >> 2, ldc = (tid & 3) * 4;
    const float* Ap = g_norm + (size_t)(mT + ldr) * NCOLS + ldc;
    const float* Bp = wo     + (size_t)(nT + ldr) * NCOLS + ldc;
    const int r0 = (tid >> 4) * 4, c0 = (tid & 15) * 4;
    float acc[4][4];
#pragma unroll
    for (int r = 0; r < 4; r++)
#pragma unroll
        for (int c = 0; c < 4; c++) acc[r][c] = 0.0f;
    for (int kt = 0; kt < 64; kt++) {
        float4 a = *(const float4*)(Ap + kt * 16);
        float4 b = *(const float4*)(Bp + kt * 16);
        As[ldc+0][ldr]=a.x; As[ldc+1][ldr]=a.y; As[ldc+2][ldr]=a.z; As[ldc+3][ldr]=a.w;
        Bs[ldc+0][ldr]=b.x; Bs[ldc+1][ldr]=b.y; Bs[ldc+2][ldr]=b.z; Bs[ldc+3][ldr]=b.w;
        __syncthreads();
#pragma unroll
        for (int kk = 0; kk < 16; kk++) {
            float4 av = *(const float4*)&As[kk][r0];
            float4 bv = *(const float4*)&Bs[kk][c0];
            float ar[4] = {av.x, av.y, av.z, av.w};
            float br[4] = {bv.x, bv.y, bv.z, bv.w};
#pragma unroll
            for (int r = 0; r < 4; r++)
#pragma unroll
                for (int c = 0; c < 4; c++) acc[r][c] += ar[r] * br[c];
        }
        __syncthreads();
    }
#pragma unroll
    for (int rr = 0; rr < 4; rr++) {
        size_t m = mT + r0 + rr;
        *(float4*)&out[m * NCOLS + nT + c0] =
            make_float4(acc[rr][0], acc[rr][1], acc[rr][2], acc[rr][3]);
    }
}

// ---------------------------------------------------------------------------
extern "C" void kernel_launch(void* const* d_in, const int* in_sizes, int n_in,
                              void* d_out, int out_size)
{
    (void)in_sizes; (void)n_in; (void)out_size;
    const float* hs  = (const float*)d_in[0];
    const float* wq  = (const float*)d_in[1];
    const float* wk  = (const float*)d_in[2];
    const float* wv  = (const float*)d_in[3];
    const float* wo  = (const float*)d_in[4];
    const float* lti = (const float*)d_in[5];
    const float* lrw = (const float*)d_in[6];
    const float* lrb = (const float*)d_in[7];
    const float* lnw = (const float*)d_in[8];
    const float* lnb = (const float*)d_in[9];
    const float* pnw = (const float*)d_in[10];
    const float* pnb = (const float*)d_in[11];
    const float* W1  = (const float*)d_in[12];
    const float* b1  = (const float*)d_in[13];
    const float* W2  = (const float*)d_in[14];
    const float* b2  = (const float*)d_in[15];
    float* out = (float*)d_out;

    cudaFuncSetAttribute(scan_kernel,
                         cudaFuncAttributeMaxDynamicSharedMemorySize,
                         (int)sizeof(SSm));

    qkv_kernel<<<dim3(16, 128, 3), 256>>>(hs, wq, wk, wv);
    lr_kernel<<<NB * NLL, 256>>>(hs, lrw, lrb);
    scan_kernel<<<2 * NB * NHEAD, 256, sizeof(SSm)>>>(W1, b1, W2, b2, lnw, lnb, lti);
    postln_kernel<<<NB * NLL, 256>>>(pnw, pnb);
    ogemm_kernel<<<dim3(16, 128), 256>>>(wo, out);
}

// round 5
// speedup vs baseline: 1.5225x; 1.1333x over previous
#include <cuda_runtime.h>
#include <math.h>
#include <stdint.h>

#define NB    4
#define NLL   2048
#define NCOLS 1024
#define NHEAD 16
#define HDIM  64
#define CK    16
#define NCH   128
#define EPSV  1e-6f

__device__ float g_XQ[NB*NHEAD*NCH*CK*HDIM];
__device__ float g_XK[NB*NHEAD*NCH*CK*HDIM];
__device__ float g_XV[NB*NHEAD*NCH*CK*HDIM];
__device__ float g_lr[NB*NHEAD*NCH*CK];
__device__ float g_XQW[NB*NLL*NCOLS];
__device__ float g_norm[NB*NLL*NCOLS];

__device__ __forceinline__ float warp_sum(float v) {
#pragma unroll
    for (int o = 16; o > 0; o >>= 1) v += __shfl_xor_sync(0xffffffffu, v, o);
    return v;
}
__device__ __forceinline__ float tanh_fast(float x) {
    float e = __expf(2.0f * x);
    return (e - 1.0f) / (e + 1.0f);
}
__device__ __forceinline__ float gelu_f(float x) {
    float t = tanh_fast(0.79788456f * x * (1.0f + 0.044715f * x * x));
    return 0.5f * x * (1.0f + t);
}
__device__ __forceinline__ float gelu_bwd_f(float x) {
    float t = tanh_fast(0.79788456f * x * (1.0f + 0.044715f * x * x));
    return 0.5f * x * ((1.0f - t * t) * (0.79788456f + 0.1070322243f * x * x))
         + 0.5f * (1.0f + t);
}
__device__ __forceinline__ uint32_t smem_u32p(const void* p) {
    uint32_t a;
    asm("{.reg .u64 t; cvta.to.shared.u64 t, %1; cvt.u32.u64 %0, t;}" : "=r"(a) : "l"(p));
    return a;
}
__device__ __forceinline__ uint32_t mapa_u32(uint32_t a, uint32_t r) {
    uint32_t o; asm("mapa.shared::cluster.u32 %0, %1, %2;" : "=r"(o) : "r"(a), "r"(r));
    return o;
}
__device__ __forceinline__ float ldc_f32(uint32_t a) {
    float v; asm volatile("ld.shared::cluster.f32 %0, [%1];" : "=f"(v) : "r"(a));
    return v;
}
#define CLUSTER_SYNC() do { \
    asm volatile("barrier.cluster.arrive.aligned;" ::: "memory"); \
    asm volatile("barrier.cluster.wait.aligned;" ::: "memory"); } while (0)

__device__ __forceinline__ uint32_t f2tf(float x) {
    uint32_t r; asm("cvt.rna.tf32.f32 %0, %1;" : "=r"(r) : "f"(x)); return r;
}
__device__ __forceinline__ void mma8(float* c, const uint32_t* a, const uint32_t* b) {
    asm volatile(
        "mma.sync.aligned.m16n8k8.row.col.f32.tf32.tf32.f32 "
        "{%0,%1,%2,%3},{%4,%5,%6,%7},{%8,%9},{%0,%1,%2,%3};"
        : "+f"(c[0]), "+f"(c[1]), "+f"(c[2]), "+f"(c[3])
        : "r"(a[0]), "r"(a[1]), "r"(a[2]), "r"(a[3]), "r"(b[0]), "r"(b[1]));
}

// ---------------------------------------------------------------------------
// K1/K5: 3xTF32 tensor-core GEMM. C[m][n] = dot(A[m], W[n]), K=1024.
// CTA 128x128, 8 warps (2m x 4n), warp 64x32. MODE 0: qkv (+RoPE+scatter),
// MODE 1: ogemm (A = g_norm, writes out).
// ---------------------------------------------------------------------------
template<int MODE>
__global__ void __launch_bounds__(256) gemm_tc(
    const float* __restrict__ Ain, const float* __restrict__ w0,
    const float* __restrict__ w1, const float* __restrict__ w2,
    float* __restrict__ outp)
{
    __shared__ uint32_t Ah[16][136], Al[16][136];
    __shared__ uint32_t Bh[128][20], Bl[128][20];

    const int z = (MODE == 0) ? blockIdx.z : 0;
    const float* Ap = (MODE == 0) ? Ain : g_norm;
    const float* W = (z == 0) ? w0 : ((z == 1) ? w1 : w2);
    float* dst = (MODE == 1) ? outp : ((z == 0) ? g_XQ : ((z == 1) ? g_XK : g_XV));

    const int mT = blockIdx.y * 128, nT = blockIdx.x * 128;
    const int tid = threadIdx.x;
    const int wi = tid >> 5, lane = tid & 31, g = lane >> 2, t4 = lane & 3;
    const int wm = (wi >> 2) * 64, wn = (wi & 3) * 32;
    const int lrow = tid >> 1, lk = (tid & 1) * 8;

    float acc[4][4][4];
#pragma unroll
    for (int mt = 0; mt < 4; mt++)
#pragma unroll
        for (int nt = 0; nt < 4; nt++)
#pragma unroll
            for (int q = 0; q < 4; q++) acc[mt][nt][q] = 0.0f;

    const float* apt = Ap + (size_t)(mT + lrow) * NCOLS + lk;
    const float* bpt = W  + (size_t)(nT + lrow) * NCOLS + lk;
    float4 a0 = *(const float4*)(apt);
    float4 a1 = *(const float4*)(apt + 4);
    float4 b0 = *(const float4*)(bpt);
    float4 b1 = *(const float4*)(bpt + 4);

#pragma unroll 1
    for (int kc = 0; kc < 64; kc++) {
        __syncthreads();
        {
            float av[8] = {a0.x,a0.y,a0.z,a0.w,a1.x,a1.y,a1.z,a1.w};
#pragma unroll
            for (int u = 0; u < 8; u++) {
                uint32_t hv = f2tf(av[u]);
                Ah[lk+u][lrow] = hv;
                Al[lk+u][lrow] = f2tf(av[u] - __uint_as_float(hv));
            }
            float bv[8] = {b0.x,b0.y,b0.z,b0.w,b1.x,b1.y,b1.z,b1.w};
            uint32_t bh[8], bl[8];
#pragma unroll
            for (int u = 0; u < 8; u++) {
                bh[u] = f2tf(bv[u]);
                bl[u] = f2tf(bv[u] - __uint_as_float(bh[u]));
            }
            *(uint4*)&Bh[lrow][lk]   = make_uint4(bh[0],bh[1],bh[2],bh[3]);
            *(uint4*)&Bh[lrow][lk+4] = make_uint4(bh[4],bh[5],bh[6],bh[7]);
            *(uint4*)&Bl[lrow][lk]   = make_uint4(bl[0],bl[1],bl[2],bl[3]);
            *(uint4*)&Bl[lrow][lk+4] = make_uint4(bl[4],bl[5],bl[6],bl[7]);
        }
        __syncthreads();
        if (kc < 63) {
            a0 = *(const float4*)(apt + (kc+1)*16);
            a1 = *(const float4*)(apt + (kc+1)*16 + 4);
            b0 = *(const float4*)(bpt + (kc+1)*16);
            b1 = *(const float4*)(bpt + (kc+1)*16 + 4);
        }
#pragma unroll
        for (int ks = 0; ks < 2; ks++) {
            uint32_t af[4][4], alf[4][4];
            const int kr = ks*8 + t4;
#pragma unroll
            for (int mt = 0; mt < 4; mt++) {
                int m0 = wm + mt*16 + g;
                af[mt][0]  = Ah[kr][m0];   af[mt][1]  = Ah[kr][m0+8];
                af[mt][2]  = Ah[kr+4][m0]; af[mt][3]  = Ah[kr+4][m0+8];
                alf[mt][0] = Al[kr][m0];   alf[mt][1] = Al[kr][m0+8];
                alf[mt][2] = Al[kr+4][m0]; alf[mt][3] = Al[kr+4][m0+8];
            }
#pragma unroll
            for (int nt = 0; nt < 4; nt++) {
                int n0 = wn + nt*8 + g;
                uint32_t bf[2]  = {Bh[n0][kr], Bh[n0][kr+4]};
                uint32_t blf[2] = {Bl[n0][kr], Bl[n0][kr+4]};
#pragma unroll
                for (int mt = 0; mt < 4; mt++) {
                    mma8(acc[mt][nt], alf[mt], bf);
                    mma8(acc[mt][nt], af[mt], blf);
                    mma8(acc[mt][nt], af[mt], bf);
                }
            }
        }
    }

#pragma unroll
    for (int mt = 0; mt < 4; mt++) {
#pragma unroll
        for (int nt = 0; nt < 4; nt++) {
#pragma unroll
            for (int half = 0; half < 2; half++) {
                int m = mT + wm + mt*16 + g + half*8;
                int n0 = nT + wn + nt*8 + 2*t4;
                float x0 = acc[mt][nt][half*2], x1 = acc[mt][nt][half*2+1];
                if (MODE == 1) {
                    *(float2*)&outp[(size_t)m * NCOLS + n0] = make_float2(x0, x1);
                } else {
                    int pos = m & 15, bb = m >> 11, l = m & 2047;
                    int nch = l >> 4, kk = l & 15;
                    int h = n0 >> 6, d = n0 & 63;
                    size_t base = ((((size_t)(bb*NHEAD + h))*NCH + nch)*CK + kk)*HDIM + d;
                    if (z < 2) {
                        float ang = (float)pos * powf(10000.0f, -((float)d) * (1.0f/64.0f));
                        float sn, cs; sincosf(ang, &sn, &cs);
                        dst[base]   = x0*cs - x1*sn;
                        dst[base+1] = x0*sn + x1*cs;
                    } else {
                        dst[base] = x0; dst[base+1] = x1;
                    }
                }
            }
        }
    }
}

// ---------------------------------------------------------------------------
// K2: ttt_lr
// ---------------------------------------------------------------------------
__global__ void __launch_bounds__(256) lr_kernel(
    const float* __restrict__ hs, const float* __restrict__ lrw,
    const float* __restrict__ lrb)
{
    int row = blockIdx.x, w = threadIdx.x >> 5, lane = threadIdx.x & 31;
    const float4* x4 = (const float4*)(hs + (size_t)row * NCOLS);
    for (int h = w; h < NHEAD; h += 8) {
        const float4* w4 = (const float4*)(lrw + (size_t)h * NCOLS);
        float acc = 0.0f;
        for (int c = lane; c < 256; c += 32) {
            float4 a = x4[c], b = w4[c];
            acc += a.x*b.x + a.y*b.y + a.z*b.z + a.w*b.w;
        }
        acc = warp_sum(acc);
        if (lane == 0) {
            float v = 1.0f / (1.0f + __expf(-(acc + lrb[h])));
            int b = row >> 11, l = row & 2047, n = l >> 4, k = l & 15;
            g_lr[(((size_t)(b*NHEAD + h))*NCH + n)*CK + k] = v * (1.0f/64.0f);
        }
    }
}

// ---------------------------------------------------------------------------
// K3: cluster-2 f-split TTT scan (unchanged from R3 WIN)
// ---------------------------------------------------------------------------
struct SSm {
    float W1[64*128];
    float W2T[64*132];
    float b1h[128], b2[64];
    float xq[16*68], xk[16*68], tg[16*68];
    float Z1[16*132];
    float X2[16*132];
    float gZ1[16*132];
    float gZ2[16*68];
    float Zp[16*68];
    float Z2[16*68];
    float Dp[16*68];
    float Z2b[16*68];
    float Sp[256];
    float A1e[256], A2e[256];
    float lr[16], le[16], tok[16];
    float lnw[64], lnb[64];
};

__global__ void __launch_bounds__(256, 1) __cluster_dims__(2, 1, 1)
scan_kernel(const float* __restrict__ W1g, const float* __restrict__ b1g,
            const float* __restrict__ W2g, const float* __restrict__ b2g,
            const float* __restrict__ lnwg, const float* __restrict__ lnbg,
            const float* __restrict__ ltig)
{
    extern __shared__ float smraw[];
    SSm& s = *reinterpret_cast<SSm*>(smraw);
    const int tid = threadIdx.x;
    const int cid = blockIdx.x >> 1;
    const int rank = blockIdx.x & 1;
    const int b = cid >> 4, h = cid & 15;
    const int foff = rank * 128;
    const uint32_t sbase = smem_u32p(smraw);
    const uint32_t pbase = mapa_u32(sbase, (uint32_t)(rank ^ 1));
    const uint32_t offZp = (uint32_t)((char*)s.Zp - (char*)&s);
    const uint32_t offSp = (uint32_t)((char*)s.Sp - (char*)&s);
    const uint32_t offDp = (uint32_t)((char*)s.Dp - (char*)&s);

    for (int i = tid; i < 8192; i += 256) {
        int d = i >> 7, fl = i & 127;
        s.W1[d*128 + fl] = W1g[(size_t)h*16384 + d*256 + foff + fl];
    }
    for (int i = tid; i < 8192; i += 256) {
        int d = i & 63, fl = i >> 6;
        s.W2T[d*132 + fl] = W2g[(size_t)h*16384 + (size_t)(foff + fl)*64 + d];
    }
    if (tid < 128) s.b1h[tid] = b1g[h*256 + foff + tid];
    if (tid < 64) {
        s.b2[tid] = b2g[h*64 + tid];
        s.lnw[tid] = lnwg[h*64 + tid];
        s.lnb[tid] = lnbg[h*64 + tid];
    }
    if (tid < 16) s.tok[tid] = fmaxf(1.0f/(float)(tid+1) + ltig[tid], 0.0f);
    __syncthreads();

    const int wi = tid >> 5, lane = tid & 31;
    const int i0 = wi * 2;
    const int f0 = lane * 4;

    for (int n = 0; n < NCH; n++) {
        {
            const float* pq = g_XQ + ((size_t)cid*NCH + n)*1024;
            const float* pk = g_XK + ((size_t)cid*NCH + n)*1024;
            const float* pv = g_XV + ((size_t)cid*NCH + n)*1024;
            int row = tid >> 4, c4 = (tid & 15) * 4;
            float4 q = *(const float4*)(pq + row*64 + c4);
            float4 k = *(const float4*)(pk + row*64 + c4);
            float4 v = *(const float4*)(pv + row*64 + c4);
            *(float4*)&s.xq[row*68 + c4] = q;
            *(float4*)&s.xk[row*68 + c4] = k;
            *(float4*)&s.tg[row*68 + c4] = make_float4(v.x-k.x, v.y-k.y, v.z-k.z, v.w-k.w);
        }
        if (tid < 16) {
            float v = g_lr[((size_t)cid*NCH + n)*CK + tid];
            s.lr[tid] = v;
            s.le[tid] = s.tok[15] * v;
        }
        __syncthreads();

        {
            int i = tid >> 4, j = tid & 15;
            const float4* q4 = (const float4*)&s.xq[i*68];
            const float4* k4 = (const float4*)&s.xk[j*68];
            float acc = 0.0f;
#pragma unroll
            for (int t = 0; t < 16; t++) {
                float4 a = q4[t], c = k4[t];
                acc += a.x*c.x + a.y*c.y + a.z*c.z + a.w*c.w;
            }
            s.A1e[tid] = (j <= i) ? s.tok[i]*s.lr[j]*(acc + 1.0f) : 0.0f;
        }

        {
            float4 bb = *(const float4*)&s.b1h[f0];
            float a00=bb.x,a01=bb.y,a02=bb.z,a03=bb.w;
            float a10=bb.x,a11=bb.y,a12=bb.z,a13=bb.w;
#pragma unroll 8
            for (int d = 0; d < 64; d++) {
                float4 w = *(const float4*)&s.W1[d*128 + f0];
                float x0 = s.xk[i0*68 + d], x1 = s.xk[(i0+1)*68 + d];
                a00 += x0*w.x; a01 += x0*w.y; a02 += x0*w.z; a03 += x0*w.w;
                a10 += x1*w.x; a11 += x1*w.y; a12 += x1*w.z; a13 += x1*w.w;
            }
            *(float4*)&s.Z1[i0*132 + f0] = make_float4(a00,a01,a02,a03);
            *(float4*)&s.Z1[(i0+1)*132 + f0] = make_float4(a10,a11,a12,a13);
            *(float4*)&s.X2[i0*132 + f0] =
                make_float4(gelu_f(a00),gelu_f(a01),gelu_f(a02),gelu_f(a03));
            *(float4*)&s.X2[(i0+1)*132 + f0] =
                make_float4(gelu_f(a10),gelu_f(a11),gelu_f(a12),gelu_f(a13));
        }
        __syncthreads();

        {
            int i = tid >> 4, dq = tid & 15;
            float acc[4] = {0,0,0,0};
            const float4* x4 = (const float4*)&s.X2[i*132];
#pragma unroll 4
            for (int t = 0; t < 32; t++) {
                float4 xv = x4[t];
#pragma unroll
                for (int jd = 0; jd < 4; jd++) {
                    float4 w = *(const float4*)&s.W2T[(dq + 16*jd)*132 + 4*t];
                    acc[jd] += xv.x*w.x + xv.y*w.y + xv.z*w.z + xv.w*w.w;
                }
            }
#pragma unroll
            for (int jd = 0; jd < 4; jd++) s.Zp[i*68 + dq + 16*jd] = acc[jd];
        }
        CLUSTER_SYNC();

        {
            int i = tid >> 4, d0 = (tid & 15) * 4;
            float4 own = *(const float4*)&s.Zp[i*68 + d0];
            uint32_t pa = pbase + offZp + (uint32_t)(i*68 + d0) * 4u;
            float4 bb = *(const float4*)&s.b2[d0];
            *(float4*)&s.Z2[i*68 + d0] = make_float4(
                own.x + ldc_f32(pa)    + bb.x, own.y + ldc_f32(pa+4)  + bb.y,
                own.z + ldc_f32(pa+8)  + bb.z, own.w + ldc_f32(pa+12) + bb.w);
        }
        __syncthreads();

        for (int rr = 0; rr < 2; rr++) {
            int i = wi*2 + rr;
            float z0 = s.Z2[i*68 + lane], z1 = s.Z2[i*68 + lane + 32];
            float mu = warp_sum(z0 + z1) * (1.0f/64.0f);
            float d0 = z0 - mu, d1 = z1 - mu;
            float var = warp_sum(d0*d0 + d1*d1) * (1.0f/64.0f);
            float rstd = rsqrtf(var + EPSV);
            float xh0 = d0*rstd, xh1 = d1*rstd;
            float w0 = s.lnw[lane], w1 = s.lnw[lane+32];
            float go0 = (w0*xh0 + s.lnb[lane]    - s.tg[i*68+lane   ]) * w0;
            float go1 = (w1*xh1 + s.lnb[lane+32] - s.tg[i*68+lane+32]) * w1;
            float sgo = warp_sum(go0 + go1);
            float sgx = warp_sum(go0*xh0 + go1*xh1);
            float sc = rstd * (1.0f/64.0f);
            s.gZ2[i*68+lane]    = (64.0f*go0 - sgo - xh0*sgx) * sc;
            s.gZ2[i*68+lane+32] = (64.0f*go1 - sgo - xh1*sgx) * sc;
        }
        __syncthreads();

        {
            float a00=0,a01=0,a02=0,a03=0,a10=0,a11=0,a12=0,a13=0;
#pragma unroll 8
            for (int d = 0; d < 64; d++) {
                float4 w = *(const float4*)&s.W2T[d*132 + f0];
                float g0 = s.gZ2[i0*68 + d], g1 = s.gZ2[(i0+1)*68 + d];
                a00 += g0*w.x; a01 += g0*w.y; a02 += g0*w.z; a03 += g0*w.w;
                a10 += g1*w.x; a11 += g1*w.y; a12 += g1*w.z; a13 += g1*w.w;
            }
            float4 z0 = *(const float4*)&s.Z1[i0*132 + f0];
            float4 z1 = *(const float4*)&s.Z1[(i0+1)*132 + f0];
            *(float4*)&s.gZ1[i0*132 + f0] = make_float4(
                a00*gelu_bwd_f(z0.x), a01*gelu_bwd_f(z0.y),
                a02*gelu_bwd_f(z0.z), a03*gelu_bwd_f(z0.w));
            *(float4*)&s.gZ1[(i0+1)*132 + f0] = make_float4(
                a10*gelu_bwd_f(z1.x), a11*gelu_bwd_f(z1.y),
                a12*gelu_bwd_f(z1.z), a13*gelu_bwd_f(z1.w));
        }
        __syncthreads();

        {
            float4 bb = *(const float4*)&s.b1h[f0];
            float a00=bb.x,a01=bb.y,a02=bb.z,a03=bb.w;
            float a10=bb.x,a11=bb.y,a12=bb.z,a13=bb.w;
#pragma unroll 8
            for (int d = 0; d < 64; d++) {
                float4 w = *(const float4*)&s.W1[d*128 + f0];
                float x0 = s.xq[i0*68 + d], x1 = s.xq[(i0+1)*68 + d];
                a00 += x0*w.x; a01 += x0*w.y; a02 += x0*w.z; a03 += x0*w.w;
                a10 += x1*w.x; a11 += x1*w.y; a12 += x1*w.z; a13 += x1*w.w;
            }
#pragma unroll
            for (int j = 0; j < 16; j++) {
                float4 g = *(const float4*)&s.gZ1[j*132 + f0];
                float e0 = s.A1e[i0*16 + j], e1 = s.A1e[(i0+1)*16 + j];
                a00 -= e0*g.x; a01 -= e0*g.y; a02 -= e0*g.z; a03 -= e0*g.w;
                a10 -= e1*g.x; a11 -= e1*g.y; a12 -= e1*g.z; a13 -= e1*g.w;
            }
            *(float4*)&s.Z1[i0*132 + f0] =
                make_float4(gelu_f(a00),gelu_f(a01),gelu_f(a02),gelu_f(a03));
            *(float4*)&s.Z1[(i0+1)*132 + f0] =
                make_float4(gelu_f(a10),gelu_f(a11),gelu_f(a12),gelu_f(a13));
        }
        __syncthreads();

        {
            int i = tid >> 4, j = tid & 15;
            const float4* x4 = (const float4*)&s.Z1[i*132];
            const float4* y4 = (const float4*)&s.X2[j*132];
            float acc = 0.0f;
#pragma unroll 8
            for (int t = 0; t < 32; t++) {
                float4 a = x4[t], c = y4[t];
                acc += a.x*c.x + a.y*c.y + a.z*c.z + a.w*c.w;
            }
            s.Sp[tid] = acc;
        }
        {
            int i = tid >> 4, dq = tid & 15;
            float acc[4] = {0,0,0,0};
            const float4* x4 = (const float4*)&s.Z1[i*132];
#pragma unroll 4
            for (int t = 0; t < 32; t++) {
                float4 xv = x4[t];
#pragma unroll
                for (int jd = 0; jd < 4; jd++) {
                    float4 w = *(const float4*)&s.W2T[(dq + 16*jd)*132 + 4*t];
                    acc[jd] += xv.x*w.x + xv.y*w.y + xv.z*w.z + xv.w*w.w;
                }
            }
#pragma unroll
            for (int jd = 0; jd < 4; jd++) s.Dp[i*68 + dq + 16*jd] = acc[jd];
        }
        CLUSTER_SYNC();

        {
            int i = tid >> 4, j = tid & 15;
            float sp = s.Sp[tid] + ldc_f32(pbase + offSp + (uint32_t)tid * 4u);
            s.A2e[tid] = (j <= i) ? s.tok[i]*s.lr[j]*(sp + 1.0f) : 0.0f;
        }
        __syncthreads();

        {
            int i = rank*8 + wi;
            int d0 = lane * 2;
            uint32_t pa = pbase + offDp + (uint32_t)(i*68 + d0) * 4u;
            float v0 = s.Dp[i*68 + d0]     + ldc_f32(pa)   + s.b2[d0];
            float v1 = s.Dp[i*68 + d0 + 1] + ldc_f32(pa+4) + s.b2[d0+1];
#pragma unroll
            for (int j = 0; j < 16; j++) {
                float a = s.A2e[i*16 + j];
                v0 -= a * s.gZ2[j*68 + d0];
                v1 -= a * s.gZ2[j*68 + d0 + 1];
            }
            s.Z2b[i*68 + d0] = v0;
            s.Z2b[i*68 + d0 + 1] = v1;
        }
        __syncthreads();

        {
            int i = rank*8 + wi;
            float z0 = s.Z2b[i*68 + lane], z1 = s.Z2b[i*68 + lane + 32];
            float mu = warp_sum(z0 + z1) * (1.0f/64.0f);
            float d0 = z0 - mu, d1 = z1 - mu;
            float var = warp_sum(d0*d0 + d1*d1) * (1.0f/64.0f);
            float rstd = rsqrtf(var + EPSV);
            float y0 = s.lnw[lane   ]*d0*rstd + s.lnb[lane   ] + s.xq[i*68+lane];
            float y1 = s.lnw[lane+32]*d1*rstd + s.lnb[lane+32] + s.xq[i*68+lane+32];
            size_t ob = ((size_t)b*NLL + (size_t)n*CK + i)*NCOLS + h*HDIM;
            g_XQW[ob + lane] = y0;
            g_XQW[ob + lane + 32] = y1;
        }

        {
#pragma unroll 1
            for (int s8 = 0; s8 < 8; s8++) {
                int d = wi + 8*s8;
                float cj[16], ej[16];
#pragma unroll
                for (int j = 0; j < 16; j++) {
                    cj[j] = s.le[j] * s.xk[j*68 + d];
                    ej[j] = s.le[j] * s.gZ2[j*68 + d];
                }
                float4 w1 = *(const float4*)&s.W1[d*128 + f0];
                float4 w2 = *(const float4*)&s.W2T[d*132 + f0];
#pragma unroll
                for (int j = 0; j < 16; j++) {
                    float4 g = *(const float4*)&s.gZ1[j*132 + f0];
                    float4 x = *(const float4*)&s.X2[j*132 + f0];
                    w1.x -= cj[j]*g.x; w1.y -= cj[j]*g.y;
                    w1.z -= cj[j]*g.z; w1.w -= cj[j]*g.w;
                    w2.x -= ej[j]*x.x; w2.y -= ej[j]*x.y;
                    w2.z -= ej[j]*x.z; w2.w -= ej[j]*x.w;
                }
                *(float4*)&s.W1[d*128 + f0]  = w1;
                *(float4*)&s.W2T[d*132 + f0] = w2;
            }
            if (tid < 128) {
                float a = s.b1h[tid];
#pragma unroll
                for (int j = 0; j < 16; j++) a -= s.le[j] * s.gZ1[j*132 + tid];
                s.b1h[tid] = a;
            }
            if (tid < 64) {
                float a = s.b2[tid];
#pragma unroll
                for (int j = 0; j < 16; j++) a -= s.le[j] * s.gZ2[j*68 + tid];
                s.b2[tid] = a;
            }
        }
        CLUSTER_SYNC();
    }
}

// ---------------------------------------------------------------------------
// K4: post layer-norm
// ---------------------------------------------------------------------------
__global__ void __launch_bounds__(256) postln_kernel(
    const float* __restrict__ pw, const float* __restrict__ pb)
{
    __shared__ float s1[8], s2[8];
    int row = blockIdx.x, tid = threadIdx.x;
    const float4* x4 = (const float4*)(g_XQW + (size_t)row * NCOLS);
    float4 a = x4[tid];
    float sum = a.x + a.y + a.z + a.w;
    float sq  = a.x*a.x + a.y*a.y + a.z*a.z + a.w*a.w;
    sum = warp_sum(sum); sq = warp_sum(sq);
    if ((tid & 31) == 0) { s1[tid>>5] = sum; s2[tid>>5] = sq; }
    __syncthreads();
    float ts = 0.0f, tq = 0.0f;
#pragma unroll
    for (int i = 0; i < 8; i++) { ts += s1[i]; tq += s2[i]; }
    float mu = ts * (1.0f/1024.0f);
    float var = tq * (1.0f/1024.0f) - mu*mu;
    float rstd = rsqrtf(var + EPSV);
    int c = tid * 4;
    float* o = g_norm + (size_t)row * NCOLS + c;
    o[0] = pw[c+0]*(a.x - mu)*rstd + pb[c+0];
    o[1] = pw[c+1]*(a.y - mu)*rstd + pb[c+1];
    o[2] = pw[c+2]*(a.z - mu)*rstd + pb[c+2];
    o[3] = pw[c+3]*(a.w - mu)*rstd + pb[c+3];
}

// ---------------------------------------------------------------------------
extern "C" void kernel_launch(void* const* d_in, const int* in_sizes, int n_in,
                              void* d_out, int out_size)
{
    (void)in_sizes; (void)n_in; (void)out_size;
    const float* hs  = (const float*)d_in[0];
    const float* wq  = (const float*)d_in[1];
    const float* wk  = (const float*)d_in[2];
    const float* wv  = (const float*)d_in[3];
    const float* wo  = (const float*)d_in[4];
    const float* lti = (const float*)d_in[5];
    const float* lrw = (const float*)d_in[6];
    const float* lrb = (const float*)d_in[7];
    const float* lnw = (const float*)d_in[8];
    const float* lnb = (const float*)d_in[9];
    const float* pnw = (const float*)d_in[10];
    const float* pnb = (const float*)d_in[11];
    const float* W1  = (const float*)d_in[12];
    const float* b1  = (const float*)d_in[13];
    const float* W2  = (const float*)d_in[14];
    const float* b2  = (const float*)d_in[15];
    float* out = (float*)d_out;

    cudaFuncSetAttribute(scan_kernel,
                         cudaFuncAttributeMaxDynamicSharedMemorySize,
                         (int)sizeof(SSm));

    gemm_tc<0><<<dim3(8, 64, 3), 256>>>(hs, wq, wk, wv, nullptr);
    lr_kernel<<<NB * NLL, 256>>>(hs, lrw, lrb);
    scan_kernel<<<2 * NB * NHEAD, 256, sizeof(SSm)>>>(W1, b1, W2, b2, lnw, lnb, lti);
    postln_kernel<<<NB * NLL, 256>>>(pnw, pnb);
    gemm_tc<1><<<dim3(8, 64), 256>>>(nullptr, wo, wo, wo, out);
}